// round 2
// baseline (speedup 1.0000x reference)
#include <cuda_runtime.h>
#include <math.h>
#include <stdint.h>

// Problem dims
#define BB 64
#define NNODE 64
#define DD 128
#define NHH 2
#define LLAYERS 2
#define ROWS (BB*NNODE)          // 4096

// ---------------- scratch (device globals; no allocation) ----------------
__device__ float g_x0 [ROWS*256];
__device__ float g_emb[ROWS*128];
__device__ float g_h  [ROWS*128];
__device__ float g_q  [ROWS*256];
__device__ float g_k  [ROWS*256];
__device__ float g_v  [ROWS*256];
__device__ float g_qe [ROWS*256];
__device__ float g_mha[ROWS*512];
__device__ float g_ffn[ROWS*512];
__device__ float g_WeT [128*128];
__device__ float g_Wbig[512*128];
__device__ float g_cvec[128];
__device__ int   g_mask_mode;    // 0 = uint8 bool, 1 = int32, 2 = float32

// ---------------- mask dtype detection ----------------
__global__ void detect_mask_kernel(const unsigned char* __restrict__ m)
{
    if (threadIdx.x == 0 && blockIdx.x == 0) {
        int u8ev = 0, f32ev = 0;
        for (int i = 0; i < 4096; i++) {
            unsigned char v = m[i];
            if (v) {
                int r = i & 3;
                if (r == 1) u8ev++;       // only raw bool has nonzero byte at offset%4==1
                else if (r == 3) f32ev++; // float 1.0f has 0x3F at offset%4==3
            }
        }
        g_mask_mode = u8ev ? 0 : (f32ev ? 2 : 1);
    }
}

__device__ __forceinline__ bool mask_at(const void* mp, size_t idx, int mode)
{
    if (mode == 0) return ((const unsigned char*)mp)[idx] != 0;
    if (mode == 1) return ((const int*)mp)[idx] != 0;
    return ((const float*)mp)[idx] != 0.0f;
}

// ---------------- concat(node_feat, stpe) -> g_x0 [4096,256] ----------------
__global__ void concat_kernel(const float* __restrict__ nf, const float* __restrict__ st)
{
    int t = blockIdx.x * blockDim.x + threadIdx.x;   // over 262144 float4
    if (t < ROWS * 64) {
        int row = t >> 6;
        int c4  = t & 63;
        float4 val;
        if (c4 < 32) val = ((const float4*)nf)[row * 32 + c4];
        else         val = ((const float4*)st)[row * 32 + (c4 - 32)];
        ((float4*)g_x0)[t] = val;
    }
}

// ---------------- LayerNorm: one warp per 128-wide row ----------------
__global__ void ln_kernel(const float* __restrict__ x, float* __restrict__ y,
                          const float* __restrict__ g, const float* __restrict__ b,
                          float eps)
{
    int row  = blockIdx.x * 8 + (threadIdx.x >> 5);
    int lane = threadIdx.x & 31;
    const float* xr = x + (size_t)row * 128;
    float v0 = xr[lane], v1 = xr[lane + 32], v2 = xr[lane + 64], v3 = xr[lane + 96];
    float s = v0 + v1 + v2 + v3;
    #pragma unroll
    for (int o = 16; o; o >>= 1) s += __shfl_xor_sync(0xffffffffu, s, o);
    float mu = s * (1.0f / 128.0f);
    float d0 = v0 - mu, d1 = v1 - mu, d2 = v2 - mu, d3 = v3 - mu;
    float q = d0*d0 + d1*d1 + d2*d2 + d3*d3;
    #pragma unroll
    for (int o = 16; o; o >>= 1) q += __shfl_xor_sync(0xffffffffu, q, o);
    float inv = rsqrtf(q * (1.0f / 128.0f) + eps);
    float* yr = y + (size_t)row * 128;
    yr[lane]      = d0 * inv * g[lane]      + b[lane];
    yr[lane + 32] = d1 * inv * g[lane + 32] + b[lane + 32];
    yr[lane + 64] = d2 * inv * g[lane + 64] + b[lane + 64];
    yr[lane + 96] = d3 * inv * g[lane + 96] + b[lane + 96];
}

// ---------------- generic fp32 GEMM: C[M,N] = A[M,K] @ B[K,N] (+bias)(+res)(relu) ----
// 64x64 block tile, 16 k-slice, 256 threads, 4x4 per-thread microtile.
__global__ void gemm_kernel(const float* __restrict__ A, int lda,
                            const float* __restrict__ B, int ldb,
                            float* __restrict__ C, int ldc,
                            int M, int N, int K,
                            const float* __restrict__ bias,
                            const float* __restrict__ res, int ldres,
                            int relu)
{
    __shared__ float sA[16][64];
    __shared__ float sB[16][64];
    int t  = threadIdx.x;
    int m0 = blockIdx.y * 64, n0 = blockIdx.x * 64;
    int tx = t & 15, ty = t >> 4;
    float acc[4][4] = {};

    int lam = t >> 2,        lak = (t & 3) * 4;   // A: row, k-quad
    int lbk = t >> 4,        lbn = (t & 15) * 4;  // B: k-row, n-quad

    for (int k0 = 0; k0 < K; k0 += 16) {
        float4 av = *(const float4*)(A + (size_t)(m0 + lam) * lda + k0 + lak);
        sA[lak + 0][lam] = av.x; sA[lak + 1][lam] = av.y;
        sA[lak + 2][lam] = av.z; sA[lak + 3][lam] = av.w;
        float4 bv = *(const float4*)(B + (size_t)(k0 + lbk) * ldb + n0 + lbn);
        *(float4*)&sB[lbk][lbn] = bv;
        __syncthreads();
        #pragma unroll
        for (int k = 0; k < 16; k++) {
            float4 a = *(float4*)&sA[k][ty * 4];
            float4 b = *(float4*)&sB[k][tx * 4];
            float ar[4] = {a.x, a.y, a.z, a.w};
            float br[4] = {b.x, b.y, b.z, b.w};
            #pragma unroll
            for (int r = 0; r < 4; r++)
                #pragma unroll
                for (int c = 0; c < 4; c++) acc[r][c] += ar[r] * br[c];
        }
        __syncthreads();
    }
    #pragma unroll
    for (int r = 0; r < 4; r++) {
        int m = m0 + ty * 4 + r;
        #pragma unroll
        for (int c = 0; c < 4; c++) {
            int n = n0 + tx * 4 + c;
            float v = acc[r][c];
            if (bias) v += bias[n];
            if (res)  v += res[(size_t)m * ldres + n];
            if (relu) v = fmaxf(v, 0.0f);
            C[(size_t)m * ldc + n] = v;
        }
    }
}

// ---------------- transpose We (128x128) -> g_WeT ----------------
__global__ void transpose_kernel(const float* __restrict__ We_l)
{
    int t = blockIdx.x * 256 + threadIdx.x;  // 16384
    if (t < 128 * 128) {
        int k = t >> 7, c = t & 127;
        g_WeT[t] = We_l[c * 128 + k];
    }
}

// ---------------- Wbig rows 0..255 = Wo_l ----------------
__global__ void copyWo_kernel(const float* __restrict__ Wo_l)
{
    int t = blockIdx.x * 256 + threadIdx.x;
    if (t < 256 * 128) g_Wbig[t] = Wo_l[t];
}

// ---------------- cvec = bo + [be,be] @ Wo ----------------
__global__ void cvec_kernel(const float* __restrict__ be_l,
                            const float* __restrict__ bo_l,
                            const float* __restrict__ Wo_l)
{
    int d = threadIdx.x;
    if (d < 128) {
        float acc = bo_l[d];
        for (int r = 0; r < 256; r++) acc += be_l[r & 127] * Wo_l[r * 128 + d];
        g_cvec[d] = acc;
    }
}

// ---------------- fused attention (no bias materialization) ----------------
// grid (4, 64): blockIdx.y = b, blockIdx.x covers 16 query rows i. 256 threads.
// scores include the q.(edge@We) term via qe and the q.be term via s_be.
// smem: k[2][64][128], v[2][64][128], edge[64][128], q[256], qe[256], sc[128],
//       att[128], be[128]
#define ATTN_SMEM_FLOATS (16384 + 16384 + 8192 + 256 + 256 + 128 + 128 + 128)
__global__ void attn_kernel(const float* __restrict__ edge,
                            const void* __restrict__ mask,
                            const float* __restrict__ be_l,
                            float* __restrict__ attn_out, int write_attn,
                            int layer)
{
    extern __shared__ float sm[];
    float* s_k   = sm;
    float* s_v   = s_k  + 16384;
    float* s_e   = s_v  + 16384;
    float* s_q   = s_e  + 8192;
    float* s_qe  = s_q  + 256;
    float* s_sc  = s_qe + 256;
    float* s_att = s_sc + 128;
    float* s_be  = s_att + 128;

    int b    = blockIdx.y;
    int i0   = blockIdx.x * 16;
    int t    = threadIdx.x;
    int lane = t & 31, w = t >> 5;
    int mode = g_mask_mode;

    // stage k,v for this batch (shared across the 16 query rows) + be
    for (int f4 = t; f4 < 4096; f4 += 256) {
        int d4 = f4 & 31, j = (f4 >> 5) & 63, h = f4 >> 11;
        float4 kv = *(const float4*)(g_k + (size_t)(b * 64 + j) * 256 + h * 128 + d4 * 4);
        *(float4*)&s_k[h * 8192 + j * 128 + d4 * 4] = kv;
        float4 vv = *(const float4*)(g_v + (size_t)(b * 64 + j) * 256 + h * 128 + d4 * 4);
        *(float4*)&s_v[h * 8192 + j * 128 + d4 * 4] = vv;
    }
    if (t < 128) s_be[t] = be_l[t];

    const float invT = 0.08838834764831843f;  // 1/sqrt(128)

    for (int ii = 0; ii < 16; ii++) {
        int i = i0 + ii;
        __syncthreads();  // protect s_e/s_q/s_att reuse from previous iteration
        // edge[b,i] tile [64,128]
        const float4* esrc = (const float4*)(edge + ((size_t)(b * 64 + i)) * 64 * 128);
        for (int f4 = t; f4 < 2048; f4 += 256)
            *(float4*)&s_e[f4 * 4] = esrc[f4];
        s_q [t] = g_q [(size_t)(b * 64 + i) * 256 + t];
        s_qe[t] = g_qe[(size_t)(b * 64 + i) * 256 + t];
        __syncthreads();

        // scores: warp w computes outputs o in [w*16, w*16+16); h fixed per warp
        {
            int h = w >> 2;
            float qr[4], qer[4];
            #pragma unroll
            for (int m = 0; m < 4; m++) {
                qr[m]  = s_q [h * 128 + lane + 32 * m];
                qer[m] = s_qe[h * 128 + lane + 32 * m];
            }
            // qb = q . be  (constant over j for this (h, i))
            float qb = 0.0f;
            #pragma unroll
            for (int m = 0; m < 4; m++) qb += qr[m] * s_be[lane + 32 * m];
            #pragma unroll
            for (int off = 16; off; off >>= 1)
                qb += __shfl_xor_sync(0xffffffffu, qb, off);

            #pragma unroll
            for (int oo = 0; oo < 16; oo++) {
                int o = w * 16 + oo;
                int j = o & 63;
                float p = 0.0f;
                #pragma unroll
                for (int m = 0; m < 4; m++) {
                    p += qr[m]  * s_k[h * 8192 + j * 128 + lane + 32 * m];
                    p += qer[m] * s_e[j * 128 + lane + 32 * m];
                }
                #pragma unroll
                for (int off = 16; off; off >>= 1)
                    p += __shfl_xor_sync(0xffffffffu, p, off);
                if (lane == 0) s_sc[o] = p + qb;
            }
        }
        __syncthreads();

        // masked softmax (warps 0,1 = heads 0,1); faithful masked_fill(1e-10)
        if (w < 2) {
            int h = w;
            size_t mbase = ((size_t)(b * 64 + i)) * 64;
            float v0 = s_sc[h * 64 + lane]      * invT;
            float v1 = s_sc[h * 64 + lane + 32] * invT;
            if (mask_at(mask, mbase + lane,      mode)) v0 = 1e-10f;
            if (mask_at(mask, mbase + lane + 32, mode)) v1 = 1e-10f;
            float mx = fmaxf(v0, v1);
            #pragma unroll
            for (int off = 16; off; off >>= 1)
                mx = fmaxf(mx, __shfl_xor_sync(0xffffffffu, mx, off));
            float e0 = expf(v0 - mx), e1 = expf(v1 - mx);
            float s = e0 + e1;
            #pragma unroll
            for (int off = 16; off; off >>= 1)
                s += __shfl_xor_sync(0xffffffffu, s, off);
            float inv = 1.0f / s;
            e0 *= inv; e1 *= inv;
            s_att[h * 64 + lane]      = e0;
            s_att[h * 64 + lane + 32] = e1;
            if (write_attn) {
                float* ap = attn_out +
                    ((((size_t)layer * NHH + h) * BB + b) * NNODE + i) * NNODE;
                ap[lane]      = e0;
                ap[lane + 32] = e1;
            }
        }
        __syncthreads();

        // emb1 = attn@v ; ew = attn@edge  (float2 per thread)
        {
            int sel = t >> 7, h = (t >> 6) & 1, d0 = (t & 63) * 2;
            float2 acc = make_float2(0.0f, 0.0f);
            const float* base = sel ? (s_e + d0) : (s_v + h * 8192 + d0);
            #pragma unroll 8
            for (int j = 0; j < 64; j++) {
                float a = s_att[h * 64 + j];
                float2 x = *(const float2*)(base + j * 128);
                acc.x += a * x.x; acc.y += a * x.y;
            }
            float* mr = g_mha + ((size_t)(b * 64 + i)) * 512 + sel * 256 + h * 128 + d0;
            mr[0] = acc.x; mr[1] = acc.y;
        }
    }
}

// ---------------- final mean over nodes ----------------
__global__ void mean_kernel(float* __restrict__ out)
{
    int b = blockIdx.x, d = threadIdx.x;
    float s = 0.0f;
    for (int n = 0; n < 64; n++) s += g_emb[(size_t)(b * 64 + n) * 128 + d];
    out[b * 128 + d] = s * (1.0f / 64.0f);
}

// ---------------- host ----------------
static inline void launch_gemm(const float* A, int lda, const float* B, int ldb,
                               float* C, int ldc, int M, int N, int K,
                               const float* bias, const float* res, int ldres, int relu)
{
    dim3 grid(N / 64, M / 64);
    gemm_kernel<<<grid, 256>>>(A, lda, B, ldb, C, ldc, M, N, K, bias, res, ldres, relu);
}

extern "C" void kernel_launch(void* const* d_in, const int* in_sizes, int n_in,
                              void* d_out, int out_size)
{
    if (n_in < 21) return;

    // Input-order detection: dict order has mask (B*N*N=262144) at index 3;
    // signature order has Wn (32768) there and mask last.
    bool dict = (in_sizes[3] == BB * NNODE * NNODE);

    const float *nf, *st, *ef, *Wn, *bn, *We, *be, *l1g, *l1b,
                *Wq, *Wk, *Wv, *Wo, *bo, *l2g, *l2b, *W1, *b1, *W2, *b2;
    const void* mask;

    if (dict) {
        nf  = (const float*)d_in[0];  st  = (const float*)d_in[1];
        ef  = (const float*)d_in[2];  mask = d_in[3];
        Wn  = (const float*)d_in[4];  bn  = (const float*)d_in[5];
        We  = (const float*)d_in[6];  be  = (const float*)d_in[7];
        l1g = (const float*)d_in[8];  l1b = (const float*)d_in[9];
        Wq  = (const float*)d_in[10]; Wk  = (const float*)d_in[11];
        Wv  = (const float*)d_in[12]; Wo  = (const float*)d_in[13];
        bo  = (const float*)d_in[14]; l2g = (const float*)d_in[15];
        l2b = (const float*)d_in[16]; W1  = (const float*)d_in[17];
        b1  = (const float*)d_in[18]; W2  = (const float*)d_in[19];
        b2  = (const float*)d_in[20];
    } else {
        nf  = (const float*)d_in[0];  st  = (const float*)d_in[1];
        ef  = (const float*)d_in[2];
        Wn  = (const float*)d_in[3];  bn  = (const float*)d_in[4];
        We  = (const float*)d_in[5];  be  = (const float*)d_in[6];
        l1g = (const float*)d_in[7];  l1b = (const float*)d_in[8];
        Wq  = (const float*)d_in[9];  Wk  = (const float*)d_in[10];
        Wv  = (const float*)d_in[11]; Wo  = (const float*)d_in[12];
        bo  = (const float*)d_in[13]; l2g = (const float*)d_in[14];
        l2b = (const float*)d_in[15]; W1  = (const float*)d_in[16];
        b1  = (const float*)d_in[17]; W2  = (const float*)d_in[18];
        b2  = (const float*)d_in[19]; mask = d_in[20];
    }

    float *p_x0, *p_emb, *p_h, *p_q, *p_k, *p_v, *p_qe, *p_mha, *p_ffn,
          *p_WeT, *p_Wbig, *p_cvec;
    cudaGetSymbolAddress((void**)&p_x0,   g_x0);
    cudaGetSymbolAddress((void**)&p_emb,  g_emb);
    cudaGetSymbolAddress((void**)&p_h,    g_h);
    cudaGetSymbolAddress((void**)&p_q,    g_q);
    cudaGetSymbolAddress((void**)&p_k,    g_k);
    cudaGetSymbolAddress((void**)&p_v,    g_v);
    cudaGetSymbolAddress((void**)&p_qe,   g_qe);
    cudaGetSymbolAddress((void**)&p_mha,  g_mha);
    cudaGetSymbolAddress((void**)&p_ffn,  g_ffn);
    cudaGetSymbolAddress((void**)&p_WeT,  g_WeT);
    cudaGetSymbolAddress((void**)&p_Wbig, g_Wbig);
    cudaGetSymbolAddress((void**)&p_cvec, g_cvec);

    const int ATTN_SMEM = ATTN_SMEM_FLOATS * 4;
    cudaFuncSetAttribute(attn_kernel, cudaFuncAttributeMaxDynamicSharedMemorySize, ATTN_SMEM);

    float* out = (float*)d_out;
    size_t need_attn = (size_t)BB * DD + (size_t)LLAYERS * NHH * BB * NNODE * NNODE;
    int write_attn = ((size_t)out_size >= need_attn) ? 1 : 0;
    float* attn_base = out + BB * DD;

    // mask dtype detection (deterministic; runs every launch)
    detect_mask_kernel<<<1, 32>>>((const unsigned char*)mask);

    // emb = cat(node, stpe) @ Wn + bn
    concat_kernel<<<(ROWS * 64 + 255) / 256, 256>>>(nf, st);
    launch_gemm(p_x0, 256, Wn, 128, p_emb, 128, ROWS, 128, 256, bn, nullptr, 0, 0);

    for (int l = 0; l < LLAYERS; l++) {
        const float* We_l = We + (size_t)l * 128 * 128;
        const float* be_l = be + (size_t)l * 128;
        const float* Wq_l = Wq + (size_t)l * 128 * 256;
        const float* Wk_l = Wk + (size_t)l * 128 * 256;
        const float* Wv_l = Wv + (size_t)l * 128 * 256;
        const float* Wo_l = Wo + (size_t)l * 256 * 128;
        const float* bo_l = bo + (size_t)l * 128;
        const float* W1_l = W1 + (size_t)l * 128 * 512;
        const float* b1_l = b1 + (size_t)l * 512;
        const float* W2_l = W2 + (size_t)l * 512 * 128;
        const float* b2_l = b2 + (size_t)l * 128;

        // pre-LN + QKV
        ln_kernel<<<512, 256>>>(p_emb, p_h, l1g + l * 128, l1b + l * 128, 1e-5f);
        launch_gemm(p_h, 128, Wq_l, 256, p_q, 256, ROWS, 256, 128, nullptr, nullptr, 0, 0);
        launch_gemm(p_h, 128, Wk_l, 256, p_k, 256, ROWS, 256, 128, nullptr, nullptr, 0, 0);
        launch_gemm(p_h, 128, Wv_l, 256, p_v, 256, ROWS, 256, 128, nullptr, nullptr, 0, 0);

        // qe = q @ We^T (per head)
        transpose_kernel<<<64, 256>>>(We_l);
        for (int h = 0; h < NHH; h++)
            launch_gemm(p_q + h * 128, 256, p_WeT, 128, p_qe + h * 128, 256,
                        ROWS, 128, 128, nullptr, nullptr, 0, 0);

        // fused attention -> g_mha rows [emb1cat | ewcat], attn probs to d_out
        attn_kernel<<<dim3(4, BB), 256, ATTN_SMEM>>>(ef, mask, be_l,
                                                     attn_base, write_attn, l);

        // Wbig = [Wo ; We@Wo_h], cvec = bo + [be,be]@Wo
        copyWo_kernel<<<128, 256>>>(Wo_l);
        for (int h = 0; h < NHH; h++)
            launch_gemm(We_l, 128, Wo_l + h * 128 * 128, 128,
                        p_Wbig + (256 + h * 128) * 128, 128,
                        128, 128, 128, nullptr, nullptr, 0, 0);
        cvec_kernel<<<1, 128>>>(be_l, bo_l, Wo_l);

        // emb = mha @ Wbig + cvec + residual
        launch_gemm(p_mha, 512, p_Wbig, 128, p_emb, 128, ROWS, 128, 512,
                    p_cvec, p_emb, 128, 0);

        // FFN
        ln_kernel<<<512, 256>>>(p_emb, p_h, l2g + l * 128, l2b + l * 128, 1e-6f);
        launch_gemm(p_h, 128, W1_l, 512, p_ffn, 512, ROWS, 512, 128,
                    b1_l, nullptr, 0, 1);
        launch_gemm(p_ffn, 512, W2_l, 128, p_emb, 128, ROWS, 128, 512,
                    b2_l, p_emb, 128, 0);
    }

    mean_kernel<<<BB, 128>>>(out);
}

// round 4
// speedup vs baseline: 1.1180x; 1.1180x over previous
#include <cuda_runtime.h>
#include <cuda_bf16.h>
#include <math.h>
#include <stdint.h>

// Problem dims
#define BB 64
#define NNODE 64
#define DD 128
#define NHH 2
#define LLAYERS 2
#define ROWS (BB*NNODE)          // 4096

// ============================================================================
// Helpers
// ============================================================================
__device__ __forceinline__ uint32_t smem_u32(const void* p) {
    uint32_t a;
    asm("{ .reg .u64 t; cvta.to.shared.u64 t, %1; cvt.u32.u64 %0, t; }"
        : "=r"(a) : "l"(p));
    return a;
}

__device__ __forceinline__ void ldmA(uint32_t* a, uint32_t addr) {
    asm volatile("ldmatrix.sync.aligned.m8n8.x4.shared.b16 {%0,%1,%2,%3}, [%4];"
        : "=r"(a[0]), "=r"(a[1]), "=r"(a[2]), "=r"(a[3]) : "r"(addr));
}
__device__ __forceinline__ void ldmB(uint32_t* b, uint32_t addr) {
    asm volatile("ldmatrix.sync.aligned.m8n8.x2.shared.b16 {%0,%1}, [%2];"
        : "=r"(b[0]), "=r"(b[1]) : "r"(addr));
}
__device__ __forceinline__ void mma16816(float* d, const uint32_t* a, const uint32_t* b) {
    asm volatile("mma.sync.aligned.m16n8k16.row.col.f32.bf16.bf16.f32 "
        "{%0,%1,%2,%3}, {%4,%5,%6,%7}, {%8,%9}, {%0,%1,%2,%3};"
        : "+f"(d[0]), "+f"(d[1]), "+f"(d[2]), "+f"(d[3])
        : "r"(a[0]), "r"(a[1]), "r"(a[2]), "r"(a[3]), "r"(b[0]), "r"(b[1]));
}

__device__ __forceinline__ void bf16split(float v, __nv_bfloat16* hi, __nv_bfloat16* lo) {
    __nv_bfloat16 h = __float2bfloat16(v);
    *hi = h;
    *lo = __float2bfloat16(v - __bfloat162float(h));
}

// ============================================================================
// Scratch (device globals; no allocation)
// ============================================================================
__device__ __nv_bfloat16 g_x0h [ROWS*256];
__device__ __nv_bfloat16 g_x0l [ROWS*256];
__device__ float         g_emb [ROWS*128];
__device__ __nv_bfloat16 g_hh  [ROWS*128];
__device__ __nv_bfloat16 g_hl  [ROWS*128];
__device__ float         g_qkv [ROWS*1024];
__device__ __nv_bfloat16 g_mhah[ROWS*512];
__device__ __nv_bfloat16 g_mhal[ROWS*512];
__device__ __nv_bfloat16 g_ffh [ROWS*512];
__device__ __nv_bfloat16 g_ffl [ROWS*512];
__device__ float         g_cvec[LLAYERS*128];
__device__ int           g_mask_mode;

// Weight images, transposed [N][K] bf16, hi plane then lo plane
__device__ __nv_bfloat16 g_WnImg  [2*128*256];
__device__ __nv_bfloat16 g_WprojImg[LLAYERS][2*1024*128];
__device__ __nv_bfloat16 g_WbigImg [LLAYERS][2*128*512];
__device__ __nv_bfloat16 g_W1Img   [LLAYERS][2*512*128];
__device__ __nv_bfloat16 g_W2Img   [LLAYERS][2*128*512];

// ============================================================================
// mask dtype detection
// ============================================================================
__global__ void detect_mask_kernel(const unsigned char* __restrict__ m)
{
    if (threadIdx.x == 0 && blockIdx.x == 0) {
        int u8ev = 0, f32ev = 0;
        for (int i = 0; i < 4096; i++) {
            unsigned char v = m[i];
            if (v) {
                int r = i & 3;
                if (r == 1) u8ev++;
                else if (r == 3) f32ev++;
            }
        }
        g_mask_mode = u8ev ? 0 : (f32ev ? 2 : 1);
    }
}
__device__ __forceinline__ bool mask_at(const void* mp, size_t idx, int mode)
{
    if (mode == 0) return ((const unsigned char*)mp)[idx] != 0;
    if (mode == 1) return ((const int*)mp)[idx] != 0;
    return ((const float*)mp)[idx] != 0.0f;
}

// ============================================================================
// Prologue: weight image prep (all write [n][K] hi + lo planes)
// ============================================================================
__global__ void wn_prep(const float* __restrict__ Wn)
{
    int t = blockIdx.x * 256 + threadIdx.x;       // 32768 = 128 n * 256 k
    if (t >= 128 * 256) return;
    int n = t >> 8, k = t & 255;
    float v = Wn[(size_t)k * 128 + n];
    __nv_bfloat16 hi, lo; bf16split(v, &hi, &lo);
    g_WnImg[(size_t)n * 256 + k]               = hi;
    g_WnImg[32768 + (size_t)n * 256 + k]       = lo;
}

// Wq/Wk/Wv -> Wproj rows 0..767
__global__ void wqkv_prep(const float* __restrict__ Wq, const float* __restrict__ Wk,
                          const float* __restrict__ Wv)
{
    int l = blockIdx.z;
    int t = blockIdx.x * 256 + threadIdx.x;       // 98304 = 768 n * 128 k
    if (t >= 768 * 128) return;
    int n = t >> 7, k = t & 127;
    const float* W = (n < 256) ? Wq : (n < 512 ? Wk : Wv);
    int col = n & 255;
    float v = W[(size_t)l * 128 * 256 + (size_t)k * 256 + col];
    __nv_bfloat16 hi, lo; bf16split(v, &hi, &lo);
    g_WprojImg[l][(size_t)n * 128 + k]          = hi;
    g_WprojImg[l][131072 + (size_t)n * 128 + k] = lo;
}

// Wqe_h[768+h*128+e][d] = sum_c Wq[d][h*128+c] * We[e][c]   (z = l*2+h)
__global__ void wqe_prep(const float* __restrict__ Wq, const float* __restrict__ We)
{
    int l = blockIdx.z >> 1, h = blockIdx.z & 1;
    int e = blockIdx.x * 16 + threadIdx.x;
    int d = blockIdx.y * 16 + threadIdx.y;
    const float* wq = Wq + (size_t)l * 128 * 256 + (size_t)d * 256 + h * 128;
    const float* we = We + (size_t)l * 128 * 128 + (size_t)e * 128;
    float acc = 0.0f;
    #pragma unroll 8
    for (int c = 0; c < 128; c++) acc += wq[c] * we[c];
    int n = 768 + h * 128 + e;
    __nv_bfloat16 hi, lo; bf16split(acc, &hi, &lo);
    g_WprojImg[l][(size_t)n * 128 + d]          = hi;
    g_WprojImg[l][131072 + (size_t)n * 128 + d] = lo;
}

// Wo -> Wbig K rows 0..255
__global__ void wo_prep(const float* __restrict__ Wo)
{
    int l = blockIdx.z;
    int t = blockIdx.x * 256 + threadIdx.x;       // 32768 = 128 n * 256 k
    if (t >= 128 * 256) return;
    int n = t >> 8, k = t & 255;
    float v = Wo[(size_t)l * 256 * 128 + (size_t)k * 128 + n];
    __nv_bfloat16 hi, lo; bf16split(v, &hi, &lo);
    g_WbigImg[l][(size_t)n * 512 + k]          = hi;
    g_WbigImg[l][65536 + (size_t)n * 512 + k]  = lo;
}

// Wbig[256+h*128+f][n] = sum_e We[f][e] * Wo[h*128+e][n]   (z = l*2+h)
__global__ void wbigc_prep(const float* __restrict__ We, const float* __restrict__ Wo)
{
    int l = blockIdx.z >> 1, h = blockIdx.z & 1;
    int n = blockIdx.x * 16 + threadIdx.x;
    int f = blockIdx.y * 16 + threadIdx.y;
    const float* we = We + (size_t)l * 128 * 128 + (size_t)f * 128;
    const float* wo = Wo + (size_t)l * 256 * 128 + (size_t)(h * 128) * 128 + n;
    float acc = 0.0f;
    #pragma unroll 8
    for (int e = 0; e < 128; e++) acc += we[e] * wo[(size_t)e * 128];
    int k = 256 + h * 128 + f;
    __nv_bfloat16 hi, lo; bf16split(acc, &hi, &lo);
    g_WbigImg[l][(size_t)n * 512 + k]          = hi;
    g_WbigImg[l][65536 + (size_t)n * 512 + k]  = lo;
}

// W1 [128,512]
__global__ void w1_prep(const float* __restrict__ W1)
{
    int l = blockIdx.z;
    int t = blockIdx.x * 256 + threadIdx.x;       // 65536 = 512 n * 128 k
    if (t >= 512 * 128) return;
    int n = t >> 7, k = t & 127;
    float v = W1[(size_t)l * 128 * 512 + (size_t)k * 512 + n];
    __nv_bfloat16 hi, lo; bf16split(v, &hi, &lo);
    g_W1Img[l][(size_t)n * 128 + k]          = hi;
    g_W1Img[l][65536 + (size_t)n * 128 + k]  = lo;
}

// W2 [512,128]
__global__ void w2_prep(const float* __restrict__ W2)
{
    int l = blockIdx.z;
    int t = blockIdx.x * 256 + threadIdx.x;       // 65536 = 128 n * 512 k
    if (t >= 128 * 512) return;
    int n = t >> 9, k = t & 511;
    float v = W2[(size_t)l * 512 * 128 + (size_t)k * 128 + n];
    __nv_bfloat16 hi, lo; bf16split(v, &hi, &lo);
    g_W2Img[l][(size_t)n * 512 + k]          = hi;
    g_W2Img[l][65536 + (size_t)n * 512 + k]  = lo;
}

// cvec[l] = bo + [be,be] @ Wo
__global__ void cvec_kernel(const float* __restrict__ be,
                            const float* __restrict__ bo,
                            const float* __restrict__ Wo)
{
    int l = blockIdx.x, d = threadIdx.x;
    float acc = bo[l * 128 + d];
    const float* wo = Wo + (size_t)l * 256 * 128;
    const float* bel = be + l * 128;
    for (int r = 0; r < 256; r++) acc += bel[r & 127] * wo[(size_t)r * 128 + d];
    g_cvec[l * 128 + d] = acc;
}

// ============================================================================
// concat(node_feat, stpe) -> bf16 pairs [4096,256]
// ============================================================================
__global__ void concat_kernel(const float* __restrict__ nf, const float* __restrict__ st)
{
    int t = blockIdx.x * blockDim.x + threadIdx.x;
    if (t < ROWS * 64) {
        int row = t >> 6, c4 = t & 63;
        float4 val = (c4 < 32) ? ((const float4*)nf)[row * 32 + c4]
                               : ((const float4*)st)[row * 32 + (c4 - 32)];
        size_t o = (size_t)row * 256 + c4 * 4;
        float vv[4] = {val.x, val.y, val.z, val.w};
        #pragma unroll
        for (int j = 0; j < 4; j++) {
            __nv_bfloat16 hi, lo; bf16split(vv[j], &hi, &lo);
            g_x0h[o + j] = hi; g_x0l[o + j] = lo;
        }
    }
}

// ============================================================================
// LayerNorm -> bf16 pairs
// ============================================================================
__global__ void ln_kernel(const float* __restrict__ x,
                          const float* __restrict__ g, const float* __restrict__ b,
                          float eps)
{
    int row  = blockIdx.x * 8 + (threadIdx.x >> 5);
    int lane = threadIdx.x & 31;
    const float* xr = x + (size_t)row * 128;
    float v0 = xr[lane], v1 = xr[lane + 32], v2 = xr[lane + 64], v3 = xr[lane + 96];
    float s = v0 + v1 + v2 + v3;
    #pragma unroll
    for (int o = 16; o; o >>= 1) s += __shfl_xor_sync(0xffffffffu, s, o);
    float mu = s * (1.0f / 128.0f);
    float d0 = v0 - mu, d1 = v1 - mu, d2 = v2 - mu, d3 = v3 - mu;
    float q = d0*d0 + d1*d1 + d2*d2 + d3*d3;
    #pragma unroll
    for (int o = 16; o; o >>= 1) q += __shfl_xor_sync(0xffffffffu, q, o);
    float inv = rsqrtf(q * (1.0f / 128.0f) + eps);
    size_t base = (size_t)row * 128;
    float y0 = d0 * inv * g[lane]      + b[lane];
    float y1 = d1 * inv * g[lane + 32] + b[lane + 32];
    float y2 = d2 * inv * g[lane + 64] + b[lane + 64];
    float y3 = d3 * inv * g[lane + 96] + b[lane + 96];
    __nv_bfloat16 hi, lo;
    bf16split(y0, &hi, &lo); g_hh[base + lane]      = hi; g_hl[base + lane]      = lo;
    bf16split(y1, &hi, &lo); g_hh[base + lane + 32] = hi; g_hl[base + lane + 32] = lo;
    bf16split(y2, &hi, &lo); g_hh[base + lane + 64] = hi; g_hl[base + lane + 64] = lo;
    bf16split(y3, &hi, &lo); g_hh[base + lane + 96] = hi; g_hl[base + lane + 96] = lo;
}

// ============================================================================
// mma.sync GEMM: C[4096, N] = A[4096, K] @ W, bf16 hi/lo split, fp32 accum.
// CTA tile 128x128, 256 threads = 8 warps (2 m x 4 n), warp tile 64x32.
// K-chunk 32. Weight image: [N][K] bf16, hi plane then lo plane.
// ============================================================================
#define KPAD 40   // 32 k + 8 pad (bf16 units); row stride 80B
__global__ __launch_bounds__(256) void mm_mma(
    const __nv_bfloat16* __restrict__ Ah, const __nv_bfloat16* __restrict__ Al,
    const __nv_bfloat16* __restrict__ Wimg, int N, int K,
    const float* __restrict__ bias,
    const float* __restrict__ res, int ldr,
    float* __restrict__ outf, int ldo,
    __nv_bfloat16* __restrict__ oh, __nv_bfloat16* __restrict__ ol, int ldp,
    int relu)
{
    __shared__ __nv_bfloat16 sAh[128 * KPAD];
    __shared__ __nv_bfloat16 sAl[128 * KPAD];
    __shared__ __nv_bfloat16 sBh[128 * KPAD];
    __shared__ __nv_bfloat16 sBl[128 * KPAD];

    int tid = threadIdx.x, lane = tid & 31, wid = tid >> 5;
    int m0 = blockIdx.y * 128, n0 = blockIdx.x * 128;
    int wm = (wid >> 2) * 64, wn = (wid & 3) * 32;

    const __nv_bfloat16* Wh = Wimg;
    const __nv_bfloat16* Wl = Wimg + (size_t)N * K;

    float acc[4][4][4];
    #pragma unroll
    for (int mt = 0; mt < 4; mt++)
        #pragma unroll
        for (int nt = 0; nt < 4; nt++)
            #pragma unroll
            for (int c = 0; c < 4; c++) acc[mt][nt][c] = 0.0f;

    uint32_t sAh_b = smem_u32(sAh), sAl_b = smem_u32(sAl);
    uint32_t sBh_b = smem_u32(sBh), sBl_b = smem_u32(sBl);

    // ldmatrix address components
    int la_row = lane & 15, la_col = (lane >> 4) * 8;        // A: x4
    int lb_row = lane & 7,  lb_col = ((lane >> 3) & 1) * 8;  // B: x2 (lanes 0-15)

    int cr = tid >> 2, cc = (tid & 3) * 8;   // copy: row, k-offset (8 bf16 = 16B)

    for (int k0 = 0; k0 < K; k0 += 32) {
        // load A/B chunk (each thread: 2 rows x 16B per buffer)
        #pragma unroll
        for (int half = 0; half < 2; half++) {
            int r = cr + half * 64;
            const uint4* ah = (const uint4*)(Ah + (size_t)(m0 + r) * K + k0 + cc);
            const uint4* al = (const uint4*)(Al + (size_t)(m0 + r) * K + k0 + cc);
            *(uint4*)(sAh + r * KPAD + cc) = *ah;
            *(uint4*)(sAl + r * KPAD + cc) = *al;
            const uint4* bh = (const uint4*)(Wh + (size_t)(n0 + r) * K + k0 + cc);
            const uint4* bl = (const uint4*)(Wl + (size_t)(n0 + r) * K + k0 + cc);
            *(uint4*)(sBh + r * KPAD + cc) = *bh;
            *(uint4*)(sBl + r * KPAD + cc) = *bl;
        }
        __syncthreads();

        #pragma unroll
        for (int ks = 0; ks < 2; ks++) {
            int kb = ks * 16;
            uint32_t bH[4][2], bL[4][2];
            #pragma unroll
            for (int nt = 0; nt < 4; nt++) {
                uint32_t boff = (uint32_t)((wn + nt * 8 + lb_row) * KPAD + kb + lb_col) * 2;
                ldmB(bH[nt], sBh_b + boff);
                ldmB(bL[nt], sBl_b + boff);
            }
            #pragma unroll
            for (int mt = 0; mt < 4; mt++) {
                uint32_t aoff = (uint32_t)((wm + mt * 16 + la_row) * KPAD + kb + la_col) * 2;
                uint32_t aH[4], aL[4];
                ldmA(aH, sAh_b + aoff);
                ldmA(aL, sAl_b + aoff);
                #pragma unroll
                for (int nt = 0; nt < 4; nt++) {
                    mma16816(acc[mt][nt], aH, bH[nt]);
                    mma16816(acc[mt][nt], aH, bL[nt]);
                    mma16816(acc[mt][nt], aL, bH[nt]);
                }
            }
        }
        __syncthreads();
    }

    // Epilogue
    int g = lane >> 2, tg = lane & 3;
    #pragma unroll
    for (int mt = 0; mt < 4; mt++) {
        #pragma unroll
        for (int nt = 0; nt < 4; nt++) {
            int col = n0 + wn + nt * 8 + tg * 2;
            #pragma unroll
            for (int half = 0; half < 2; half++) {
                int row = m0 + wm + mt * 16 + g + half * 8;
                float v0 = acc[mt][nt][half * 2];
                float v1 = acc[mt][nt][half * 2 + 1];
                if (bias) { v0 += bias[col]; v1 += bias[col + 1]; }
                if (res) {
                    v0 += res[(size_t)row * ldr + col];
                    v1 += res[(size_t)row * ldr + col + 1];
                }
                if (relu) { v0 = fmaxf(v0, 0.0f); v1 = fmaxf(v1, 0.0f); }
                if (outf) {
                    outf[(size_t)row * ldo + col]     = v0;
                    outf[(size_t)row * ldo + col + 1] = v1;
                }
                if (oh) {
                    __nv_bfloat16 hi, lo;
                    bf16split(v0, &hi, &lo);
                    oh[(size_t)row * ldp + col] = hi;
                    ol[(size_t)row * ldp + col] = lo;
                    bf16split(v1, &hi, &lo);
                    oh[(size_t)row * ldp + col + 1] = hi;
                    ol[(size_t)row * ldp + col + 1] = lo;
                }
            }
        }
    }
}

// ============================================================================
// fused attention (reads g_qkv fp32, writes mha bf16 pairs + attn probs)
// grid (4, 64): blockIdx.y = b, blockIdx.x covers 16 query rows. 256 threads.
// ============================================================================
#define ATTN_SMEM_FLOATS (16384 + 16384 + 8192 + 256 + 256 + 128 + 128 + 128)
__global__ void attn_kernel(const float* __restrict__ edge,
                            const void* __restrict__ mask,
                            const float* __restrict__ be_l,
                            float* __restrict__ attn_out, int write_attn,
                            int layer)
{
    extern __shared__ float sm[];
    float* s_k   = sm;
    float* s_v   = s_k  + 16384;
    float* s_e   = s_v  + 16384;
    float* s_q   = s_e  + 8192;
    float* s_qe  = s_q  + 256;
    float* s_sc  = s_qe + 256;
    float* s_att = s_sc + 128;
    float* s_be  = s_att + 128;

    int b    = blockIdx.y;
    int i0   = blockIdx.x * 16;
    int t    = threadIdx.x;
    int lane = t & 31, w = t >> 5;
    int mode = g_mask_mode;

    // stage k,v (qkv layout: q 0..255, k 256..511, v 512..767, qe 768..1023)
    for (int f4 = t; f4 < 4096; f4 += 256) {
        int d4 = f4 & 31, j = (f4 >> 5) & 63, h = f4 >> 11;
        float4 kv = *(const float4*)(g_qkv + (size_t)(b * 64 + j) * 1024 + 256 + h * 128 + d4 * 4);
        *(float4*)&s_k[h * 8192 + j * 128 + d4 * 4] = kv;
        float4 vv = *(const float4*)(g_qkv + (size_t)(b * 64 + j) * 1024 + 512 + h * 128 + d4 * 4);
        *(float4*)&s_v[h * 8192 + j * 128 + d4 * 4] = vv;
    }
    if (t < 128) s_be[t] = be_l[t];

    const float invT = 0.08838834764831843f;  // 1/sqrt(128)

    for (int ii = 0; ii < 16; ii++) {
        int i = i0 + ii;
        __syncthreads();
        const float4* esrc = (const float4*)(edge + ((size_t)(b * 64 + i)) * 64 * 128);
        for (int f4 = t; f4 < 2048; f4 += 256)
            *(float4*)&s_e[f4 * 4] = esrc[f4];
        s_q [t] = g_qkv[(size_t)(b * 64 + i) * 1024 + t];
        s_qe[t] = g_qkv[(size_t)(b * 64 + i) * 1024 + 768 + t];
        __syncthreads();

        // scores
        {
            int h = w >> 2;
            float qr[4], qer[4];
            #pragma unroll
            for (int mth = 0; mth < 4; mth++) {
                qr[mth]  = s_q [h * 128 + lane + 32 * mth];
                qer[mth] = s_qe[h * 128 + lane + 32 * mth];
            }
            float qb = 0.0f;
            #pragma unroll
            for (int mth = 0; mth < 4; mth++) qb += qr[mth] * s_be[lane + 32 * mth];
            #pragma unroll
            for (int off = 16; off; off >>= 1)
                qb += __shfl_xor_sync(0xffffffffu, qb, off);

            #pragma unroll
            for (int oo = 0; oo < 16; oo++) {
                int o = w * 16 + oo;
                int j = o & 63;
                float p = 0.0f;
                #pragma unroll
                for (int mth = 0; mth < 4; mth++) {
                    p += qr[mth]  * s_k[h * 8192 + j * 128 + lane + 32 * mth];
                    p += qer[mth] * s_e[j * 128 + lane + 32 * mth];
                }
                #pragma unroll
                for (int off = 16; off; off >>= 1)
                    p += __shfl_xor_sync(0xffffffffu, p, off);
                if (lane == 0) s_sc[o] = p + qb;
            }
        }
        __syncthreads();

        // masked softmax; faithful masked_fill(1e-10)
        if (w < 2) {
            int h = w;
            size_t mbase = ((size_t)(b * 64 + i)) * 64;
            float v0 = s_sc[h * 64 + lane]      * invT;
            float v1 = s_sc[h * 64 + lane + 32] * invT;
            if (mask_at(mask, mbase + lane,      mode)) v0 = 1e-10f;
            if (mask_at(mask, mbase + lane + 32, mode)) v1 = 1e-10f;
            float mx = fmaxf(v0, v1);
            #pragma unroll
            for (int off = 16; off; off >>= 1)
                mx = fmaxf(mx, __shfl_xor_sync(0xffffffffu, mx, off));
            float e0 = expf(v0 - mx), e1 = expf(v1 - mx);
            float s = e0 + e1;
            #pragma unroll
            for (int off = 16; off; off >>= 1)
                s += __shfl_xor_sync(0xffffffffu, s, off);
            float inv = 1.0f / s;
            e0 *= inv; e1 *= inv;
            s_att[h * 64 + lane]      = e0;
            s_att[h * 64 + lane + 32] = e1;
            if (write_attn) {
                float* ap = attn_out +
                    ((((size_t)layer * NHH + h) * BB + b) * NNODE + i) * NNODE;
                ap[lane]      = e0;
                ap[lane + 32] = e1;
            }
        }
        __syncthreads();

        // emb1 = attn@v ; ew = attn@edge; write bf16 pairs
        {
            int sel = t >> 7, h = (t >> 6) & 1, d0 = (t & 63) * 2;
            float2 acc = make_float2(0.0f, 0.0f);
            const float* base = sel ? (s_e + d0) : (s_v + h * 8192 + d0);
            #pragma unroll 8
            for (int j = 0; j < 64; j++) {
                float a = s_att[h * 64 + j];
                float2 x = *(const float2*)(base + j * 128);
                acc.x += a * x.x; acc.y += a * x.y;
            }
            size_t mo = ((size_t)(b * 64 + i)) * 512 + sel * 256 + h * 128 + d0;
            __nv_bfloat16 hi, lo;
            bf16split(acc.x, &hi, &lo); g_mhah[mo]     = hi; g_mhal[mo]     = lo;
            bf16split(acc.y, &hi, &lo); g_mhah[mo + 1] = hi; g_mhal[mo + 1] = lo;
        }
    }
}

// ---------------- final mean over nodes ----------------
__global__ void mean_kernel(float* __restrict__ out)
{
    int b = blockIdx.x, d = threadIdx.x;
    float s = 0.0f;
    for (int n = 0; n < 64; n++) s += g_emb[(size_t)(b * 64 + n) * 128 + d];
    out[b * 128 + d] = s * (1.0f / 64.0f);
}

// ============================================================================
// host
// ============================================================================
extern "C" void kernel_launch(void* const* d_in, const int* in_sizes, int n_in,
                              void* d_out, int out_size)
{
    if (n_in < 21) return;
    bool dict = (in_sizes[3] == BB * NNODE * NNODE);

    const float *nf, *st, *ef, *Wn, *bn, *We, *be, *l1g, *l1b,
                *Wq, *Wk, *Wv, *Wo, *bo, *l2g, *l2b, *W1, *b1, *W2, *b2;
    const void* mask;

    if (dict) {
        nf  = (const float*)d_in[0];  st  = (const float*)d_in[1];
        ef  = (const float*)d_in[2];  mask = d_in[3];
        Wn  = (const float*)d_in[4];  bn  = (const float*)d_in[5];
        We  = (const float*)d_in[6];  be  = (const float*)d_in[7];
        l1g = (const float*)d_in[8];  l1b = (const float*)d_in[9];
        Wq  = (const float*)d_in[10]; Wk  = (const float*)d_in[11];
        Wv  = (const float*)d_in[12]; Wo  = (const float*)d_in[13];
        bo  = (const float*)d_in[14]; l2g = (const float*)d_in[15];
        l2b = (const float*)d_in[16]; W1  = (const float*)d_in[17];
        b1  = (const float*)d_in[18]; W2  = (const float*)d_in[19];
        b2  = (const float*)d_in[20];
    } else {
        nf  = (const float*)d_in[0];  st  = (const float*)d_in[1];
        ef  = (const float*)d_in[2];
        Wn  = (const float*)d_in[3];  bn  = (const float*)d_in[4];
        We  = (const float*)d_in[5];  be  = (const float*)d_in[6];
        l1g = (const float*)d_in[7];  l1b = (const float*)d_in[8];
        Wq  = (const float*)d_in[9];  Wk  = (const float*)d_in[10];
        Wv  = (const float*)d_in[11]; Wo  = (const float*)d_in[12];
        bo  = (const float*)d_in[13]; l2g = (const float*)d_in[14];
        l2b = (const float*)d_in[15]; W1  = (const float*)d_in[16];
        b1  = (const float*)d_in[17]; W2  = (const float*)d_in[18];
        b2  = (const float*)d_in[19]; mask = d_in[20];
    }

    float *p_emb, *p_cvec, *p_qkv;
    __nv_bfloat16 *p_x0h, *p_x0l, *p_hh, *p_hl, *p_mhah, *p_mhal, *p_ffh, *p_ffl;
    __nv_bfloat16 *p_WnImg, *p_WprojImg, *p_WbigImg, *p_W1Img, *p_W2Img;
    cudaGetSymbolAddress((void**)&p_emb,   g_emb);
    cudaGetSymbolAddress((void**)&p_cvec,  g_cvec);
    cudaGetSymbolAddress((void**)&p_x0h,   g_x0h);
    cudaGetSymbolAddress((void**)&p_x0l,   g_x0l);
    cudaGetSymbolAddress((void**)&p_hh,    g_hh);
    cudaGetSymbolAddress((void**)&p_hl,    g_hl);
    cudaGetSymbolAddress((void**)&p_mhah,  g_mhah);
    cudaGetSymbolAddress((void**)&p_mhal,  g_mhal);
    cudaGetSymbolAddress((void**)&p_ffh,   g_ffh);
    cudaGetSymbolAddress((void**)&p_ffl,   g_ffl);
    cudaGetSymbolAddress((void**)&p_qkv,   g_qkv);
    cudaGetSymbolAddress((void**)&p_WnImg,   g_WnImg);
    cudaGetSymbolAddress((void**)&p_WprojImg, g_WprojImg);
    cudaGetSymbolAddress((void**)&p_WbigImg,  g_WbigImg);
    cudaGetSymbolAddress((void**)&p_W1Img,    g_W1Img);
    cudaGetSymbolAddress((void**)&p_W2Img,    g_W2Img);

    const int ATTN_SMEM = ATTN_SMEM_FLOATS * 4;
    cudaFuncSetAttribute(attn_kernel, cudaFuncAttributeMaxDynamicSharedMemorySize, ATTN_SMEM);

    float* out = (float*)d_out;
    size_t need_attn = (size_t)BB * DD + (size_t)LLAYERS * NHH * BB * NNODE * NNODE;
    int write_attn = ((size_t)out_size >= need_attn) ? 1 : 0;
    float* attn_base = out + BB * DD;

    detect_mask_kernel<<<1, 32>>>((const unsigned char*)mask);
    concat_kernel<<<(ROWS * 64 + 255) / 256, 256>>>(nf, st);

    // weight prep (activation-independent)
    wn_prep<<<128, 256>>>(Wn);
    wqkv_prep<<<dim3(384, 1, LLAYERS), 256>>>(Wq, Wk, Wv);
    wqe_prep<<<dim3(8, 8, 2 * LLAYERS), dim3(16, 16)>>>(Wq, We);
    wo_prep<<<dim3(128, 1, LLAYERS), 256>>>(Wo);
    wbigc_prep<<<dim3(8, 8, 2 * LLAYERS), dim3(16, 16)>>>(We, Wo);
    w1_prep<<<dim3(256, 1, LLAYERS), 256>>>(W1);
    w2_prep<<<dim3(256, 1, LLAYERS), 256>>>(W2);
    cvec_kernel<<<LLAYERS, 128>>>(be, bo, Wo);

    // emb = cat(node, stpe) @ Wn + bn
    mm_mma<<<dim3(1, 32), 256>>>(p_x0h, p_x0l, p_WnImg, 128, 256,
        bn, nullptr, 0, p_emb, 128, nullptr, nullptr, 0, 0);

    for (int l = 0; l < LLAYERS; l++) {
        const float* be_l = be + (size_t)l * 128;
        // pre-LN + fused q|k|v|qe projection (N=1024)
        ln_kernel<<<512, 256>>>(p_emb, l1g + l * 128, l1b + l * 128, 1e-5f);
        mm_mma<<<dim3(8, 32), 256>>>(p_hh, p_hl,
            p_WprojImg + (size_t)l * 2 * 1024 * 128, 1024, 128,
            nullptr, nullptr, 0, p_qkv, 1024, nullptr, nullptr, 0, 0);

        // fused attention
        attn_kernel<<<dim3(4, BB), 256, ATTN_SMEM>>>(ef, mask, be_l,
                                                     attn_base, write_attn, l);

        // emb = mha @ Wbig + cvec + residual
        mm_mma<<<dim3(1, 32), 256>>>(p_mhah, p_mhal,
            p_WbigImg + (size_t)l * 2 * 128 * 512, 128, 512,
            p_cvec + l * 128, p_emb, 128, p_emb, 128, nullptr, nullptr, 0, 0);

        // FFN
        ln_kernel<<<512, 256>>>(p_emb, l2g + l * 128, l2b + l * 128, 1e-6f);
        mm_mma<<<dim3(4, 32), 256>>>(p_hh, p_hl,
            p_W1Img + (size_t)l * 2 * 512 * 128, 512, 128,
            b1 + (size_t)l * 512, nullptr, 0, nullptr, 0, p_ffh, p_ffl, 512, 1);
        mm_mma<<<dim3(1, 32), 256>>>(p_ffh, p_ffl,
            p_W2Img + (size_t)l * 2 * 128 * 512, 128, 512,
            b2 + (size_t)l * 128, p_emb, 128, p_emb, 128, nullptr, nullptr, 0, 0);
    }

    mean_kernel<<<BB, 128>>>(out);
}

// round 5
// speedup vs baseline: 1.2338x; 1.1036x over previous
#include <cuda_runtime.h>
#include <cuda_bf16.h>
#include <math.h>
#include <stdint.h>

// Problem dims
#define BB 64
#define NNODE 64
#define DD 128
#define NHH 2
#define LLAYERS 2
#define ROWS (BB*NNODE)          // 4096

// ============================================================================
// Helpers
// ============================================================================
__device__ __forceinline__ uint32_t smem_u32(const void* p) {
    uint32_t a;
    asm("{ .reg .u64 t; cvta.to.shared.u64 t, %1; cvt.u32.u64 %0, t; }"
        : "=r"(a) : "l"(p));
    return a;
}

__device__ __forceinline__ void ldmA(uint32_t* a, uint32_t addr) {
    asm volatile("ldmatrix.sync.aligned.m8n8.x4.shared.b16 {%0,%1,%2,%3}, [%4];"
        : "=r"(a[0]), "=r"(a[1]), "=r"(a[2]), "=r"(a[3]) : "r"(addr));
}
__device__ __forceinline__ void ldmBt(uint32_t* b, uint32_t addr) {
    asm volatile("ldmatrix.sync.aligned.m8n8.x2.trans.shared.b16 {%0,%1}, [%2];"
        : "=r"(b[0]), "=r"(b[1]) : "r"(addr));
}
__device__ __forceinline__ void mma16816(float* d, const uint32_t* a, const uint32_t* b) {
    asm volatile("mma.sync.aligned.m16n8k16.row.col.f32.bf16.bf16.f32 "
        "{%0,%1,%2,%3}, {%4,%5,%6,%7}, {%8,%9}, {%0,%1,%2,%3};"
        : "+f"(d[0]), "+f"(d[1]), "+f"(d[2]), "+f"(d[3])
        : "r"(a[0]), "r"(a[1]), "r"(a[2]), "r"(a[3]), "r"(b[0]), "r"(b[1]));
}

__device__ __forceinline__ void bf16split(float v, __nv_bfloat16* hi, __nv_bfloat16* lo) {
    __nv_bfloat16 h = __float2bfloat16(v);
    *hi = h;
    *lo = __float2bfloat16(v - __bfloat162float(h));
}

// ============================================================================
// Scratch (device globals; no allocation)
// ============================================================================
__device__ __nv_bfloat16 g_x0h [ROWS*256];
__device__ __nv_bfloat16 g_x0l [ROWS*256];
__device__ float         g_emb [ROWS*128];
__device__ __nv_bfloat16 g_hh  [ROWS*128];
__device__ __nv_bfloat16 g_hl  [ROWS*128];
__device__ float         g_qkv [ROWS*1024];
__device__ __nv_bfloat16 g_mhah[ROWS*512];
__device__ __nv_bfloat16 g_mhal[ROWS*512];
__device__ __nv_bfloat16 g_ffh [ROWS*512];
__device__ __nv_bfloat16 g_ffl [ROWS*512];
__device__ float         g_cvec[LLAYERS*128];
__device__ int           g_mask_mode;

// Weight images, natural [K][N] bf16, hi plane then lo plane
__device__ __nv_bfloat16 g_WnImg  [2*256*128];
__device__ __nv_bfloat16 g_WprojImg[LLAYERS][2*128*1024];
__device__ __nv_bfloat16 g_WbigImg [LLAYERS][2*512*128];
__device__ __nv_bfloat16 g_W1Img   [LLAYERS][2*128*512];
__device__ __nv_bfloat16 g_W2Img   [LLAYERS][2*512*128];

// ============================================================================
// mask dtype detection (parallel)
// ============================================================================
__global__ void detect_mask_kernel(const unsigned char* __restrict__ m)
{
    __shared__ int cnt[2];
    if (threadIdx.x < 2) cnt[threadIdx.x] = 0;
    __syncthreads();
    int u8 = 0, f32 = 0;
    for (int i = threadIdx.x; i < 4096; i += 256) {
        unsigned char v = m[i];
        if (v) {
            int r = i & 3;
            if (r == 1) u8++;
            else if (r == 3) f32++;
        }
    }
    if (u8)  atomicAdd(&cnt[0], u8);
    if (f32) atomicAdd(&cnt[1], f32);
    __syncthreads();
    if (threadIdx.x == 0)
        g_mask_mode = cnt[0] ? 0 : (cnt[1] ? 2 : 1);
}
__device__ __forceinline__ bool mask_at(const void* mp, size_t idx, int mode)
{
    if (mode == 0) return ((const unsigned char*)mp)[idx] != 0;
    if (mode == 1) return ((const int*)mp)[idx] != 0;
    return ((const float*)mp)[idx] != 0.0f;
}

// ============================================================================
// Prologue: weight image prep — natural [K][N], coalesced convert-copy
// ============================================================================
__global__ void wn_prep(const float* __restrict__ Wn)
{
    int t = blockIdx.x * 256 + threadIdx.x;    // 32768, linear
    if (t >= 256 * 128) return;
    __nv_bfloat16 hi, lo; bf16split(Wn[t], &hi, &lo);
    g_WnImg[t] = hi; g_WnImg[32768 + t] = lo;
}

// Wq/Wk/Wv -> Wproj cols 0..767 of [128][1024]
__global__ void wqkv_prep(const float* __restrict__ Wq, const float* __restrict__ Wk,
                          const float* __restrict__ Wv)
{
    int l = blockIdx.z;
    int t = blockIdx.x * 256 + threadIdx.x;    // 98304 = 128 k * 768 n
    if (t >= 128 * 768) return;
    int k = t / 768, n = t % 768;
    const float* W = (n < 256) ? Wq : (n < 512 ? Wk : Wv);
    float v = W[(size_t)l * 128 * 256 + (size_t)k * 256 + (n & 255)];
    __nv_bfloat16 hi, lo; bf16split(v, &hi, &lo);
    g_WprojImg[l][(size_t)k * 1024 + n]          = hi;
    g_WprojImg[l][131072 + (size_t)k * 1024 + n] = lo;
}

// Wqe: Wproj[d][768+h*128+e] = sum_c Wq[d][h*128+c] * We[e][c]   (z = l*2+h)
__global__ void wqe_prep(const float* __restrict__ Wq, const float* __restrict__ We)
{
    int l = blockIdx.z >> 1, h = blockIdx.z & 1;
    int e = blockIdx.x * 16 + threadIdx.x;
    int d = blockIdx.y * 16 + threadIdx.y;
    const float* wq = Wq + (size_t)l * 128 * 256 + (size_t)d * 256 + h * 128;
    const float* we = We + (size_t)l * 128 * 128 + (size_t)e * 128;
    float acc = 0.0f;
    #pragma unroll 8
    for (int c = 0; c < 128; c++) acc += wq[c] * we[c];
    size_t o = (size_t)d * 1024 + 768 + h * 128 + e;
    __nv_bfloat16 hi, lo; bf16split(acc, &hi, &lo);
    g_WprojImg[l][o] = hi; g_WprojImg[l][131072 + o] = lo;
}

// Wo -> Wbig rows 0..255 of [512][128]
__global__ void wo_prep(const float* __restrict__ Wo)
{
    int l = blockIdx.z;
    int t = blockIdx.x * 256 + threadIdx.x;    // 32768, linear
    if (t >= 256 * 128) return;
    __nv_bfloat16 hi, lo; bf16split(Wo[(size_t)l * 32768 + t], &hi, &lo);
    g_WbigImg[l][t] = hi; g_WbigImg[l][65536 + t] = lo;
}

// Wbig[256+h*128+f][n] = sum_e We[f][e] * Wo[h*128+e][n]   (z = l*2+h)
__global__ void wbigc_prep(const float* __restrict__ We, const float* __restrict__ Wo)
{
    int l = blockIdx.z >> 1, h = blockIdx.z & 1;
    int n = blockIdx.x * 16 + threadIdx.x;
    int f = blockIdx.y * 16 + threadIdx.y;
    const float* we = We + (size_t)l * 128 * 128 + (size_t)f * 128;
    const float* wo = Wo + (size_t)l * 256 * 128 + (size_t)(h * 128) * 128 + n;
    float acc = 0.0f;
    #pragma unroll 8
    for (int e = 0; e < 128; e++) acc += we[e] * wo[(size_t)e * 128];
    size_t o = (size_t)(256 + h * 128 + f) * 128 + n;
    __nv_bfloat16 hi, lo; bf16split(acc, &hi, &lo);
    g_WbigImg[l][o] = hi; g_WbigImg[l][65536 + o] = lo;
}

// W1 [128][512], linear
__global__ void w1_prep(const float* __restrict__ W1)
{
    int l = blockIdx.z;
    int t = blockIdx.x * 256 + threadIdx.x;
    if (t >= 128 * 512) return;
    __nv_bfloat16 hi, lo; bf16split(W1[(size_t)l * 65536 + t], &hi, &lo);
    g_W1Img[l][t] = hi; g_W1Img[l][65536 + t] = lo;
}

// W2 [512][128], linear
__global__ void w2_prep(const float* __restrict__ W2)
{
    int l = blockIdx.z;
    int t = blockIdx.x * 256 + threadIdx.x;
    if (t >= 512 * 128) return;
    __nv_bfloat16 hi, lo; bf16split(W2[(size_t)l * 65536 + t], &hi, &lo);
    g_W2Img[l][t] = hi; g_W2Img[l][65536 + t] = lo;
}

// cvec[l] = bo + [be,be] @ Wo
__global__ void cvec_kernel(const float* __restrict__ be,
                            const float* __restrict__ bo,
                            const float* __restrict__ Wo)
{
    int l = blockIdx.x, d = threadIdx.x;
    float acc = bo[l * 128 + d];
    const float* wo = Wo + (size_t)l * 256 * 128;
    const float* bel = be + l * 128;
    for (int r = 0; r < 256; r++) acc += bel[r & 127] * wo[(size_t)r * 128 + d];
    g_cvec[l * 128 + d] = acc;
}

// ============================================================================
// concat(node_feat, stpe) -> bf16 pairs [4096,256]
// ============================================================================
__global__ void concat_kernel(const float* __restrict__ nf, const float* __restrict__ st)
{
    int t = blockIdx.x * blockDim.x + threadIdx.x;
    if (t < ROWS * 64) {
        int row = t >> 6, c4 = t & 63;
        float4 val = (c4 < 32) ? ((const float4*)nf)[row * 32 + c4]
                               : ((const float4*)st)[row * 32 + (c4 - 32)];
        size_t o = (size_t)row * 256 + c4 * 4;
        float vv[4] = {val.x, val.y, val.z, val.w};
        #pragma unroll
        for (int j = 0; j < 4; j++) {
            __nv_bfloat16 hi, lo; bf16split(vv[j], &hi, &lo);
            g_x0h[o + j] = hi; g_x0l[o + j] = lo;
        }
    }
}

// ============================================================================
// LayerNorm -> bf16 pairs
// ============================================================================
__global__ void ln_kernel(const float* __restrict__ x,
                          const float* __restrict__ g, const float* __restrict__ b,
                          float eps)
{
    int row  = blockIdx.x * 8 + (threadIdx.x >> 5);
    int lane = threadIdx.x & 31;
    const float* xr = x + (size_t)row * 128;
    float v0 = xr[lane], v1 = xr[lane + 32], v2 = xr[lane + 64], v3 = xr[lane + 96];
    float s = v0 + v1 + v2 + v3;
    #pragma unroll
    for (int o = 16; o; o >>= 1) s += __shfl_xor_sync(0xffffffffu, s, o);
    float mu = s * (1.0f / 128.0f);
    float d0 = v0 - mu, d1 = v1 - mu, d2 = v2 - mu, d3 = v3 - mu;
    float q = d0*d0 + d1*d1 + d2*d2 + d3*d3;
    #pragma unroll
    for (int o = 16; o; o >>= 1) q += __shfl_xor_sync(0xffffffffu, q, o);
    float inv = rsqrtf(q * (1.0f / 128.0f) + eps);
    size_t base = (size_t)row * 128;
    float y0 = d0 * inv * g[lane]      + b[lane];
    float y1 = d1 * inv * g[lane + 32] + b[lane + 32];
    float y2 = d2 * inv * g[lane + 64] + b[lane + 64];
    float y3 = d3 * inv * g[lane + 96] + b[lane + 96];
    __nv_bfloat16 hi, lo;
    bf16split(y0, &hi, &lo); g_hh[base + lane]      = hi; g_hl[base + lane]      = lo;
    bf16split(y1, &hi, &lo); g_hh[base + lane + 32] = hi; g_hl[base + lane + 32] = lo;
    bf16split(y2, &hi, &lo); g_hh[base + lane + 64] = hi; g_hl[base + lane + 64] = lo;
    bf16split(y3, &hi, &lo); g_hh[base + lane + 96] = hi; g_hl[base + lane + 96] = lo;
}

// ============================================================================
// mma.sync GEMM: C[4096, N] = A[4096, K] @ W, bf16 hi/lo split, fp32 accum.
// CTA tile 64x64, 128 threads = 4 warps (2m x 2n), warp tile 32x32.
// K-chunk 32. Weight image: [K][N] bf16 (hi plane, then lo plane);
// B fragments via ldmatrix.trans.
// ============================================================================
#define AKP 40   // A smem row stride (32 k + 8 pad) bf16
#define BNP 72   // B smem row stride (64 n + 8 pad) bf16; 144B (odd 16B units)
__global__ __launch_bounds__(128) void mm_mma(
    const __nv_bfloat16* __restrict__ Ah, const __nv_bfloat16* __restrict__ Al,
    const __nv_bfloat16* __restrict__ Wimg, int N, int K,
    const float* __restrict__ bias,
    const float* __restrict__ res, int ldr,
    float* __restrict__ outf, int ldo,
    __nv_bfloat16* __restrict__ oh, __nv_bfloat16* __restrict__ ol, int ldp,
    int relu)
{
    __shared__ __nv_bfloat16 sAh[64 * AKP];
    __shared__ __nv_bfloat16 sAl[64 * AKP];
    __shared__ __nv_bfloat16 sBh[32 * BNP];
    __shared__ __nv_bfloat16 sBl[32 * BNP];

    int tid = threadIdx.x, lane = tid & 31, wid = tid >> 5;
    int m0 = blockIdx.y * 64, n0 = blockIdx.x * 64;
    int wm = (wid >> 1) * 32, wn = (wid & 1) * 32;

    const __nv_bfloat16* Wh = Wimg;
    const __nv_bfloat16* Wl = Wimg + (size_t)N * K;

    float acc[2][4][4];
    #pragma unroll
    for (int mt = 0; mt < 2; mt++)
        #pragma unroll
        for (int nt = 0; nt < 4; nt++)
            #pragma unroll
            for (int c = 0; c < 4; c++) acc[mt][nt][c] = 0.0f;

    uint32_t sAh_b = smem_u32(sAh), sAl_b = smem_u32(sAl);
    uint32_t sBh_b = smem_u32(sBh), sBl_b = smem_u32(sBl);

    int la_row = lane & 15, la_col = (lane >> 4) * 8;   // A x4
    int lb_row = lane & 15;                             // B x2 trans (lanes 0-15)

    for (int k0 = 0; k0 < K; k0 += 32) {
        #pragma unroll
        for (int i = 0; i < 2; i++) {
            int idx = tid + i * 128;
            int ar = idx >> 2, ac = (idx & 3) * 8;      // A: 64 rows x 32 k
            *(uint4*)(sAh + ar * AKP + ac) =
                *(const uint4*)(Ah + (size_t)(m0 + ar) * K + k0 + ac);
            *(uint4*)(sAl + ar * AKP + ac) =
                *(const uint4*)(Al + (size_t)(m0 + ar) * K + k0 + ac);
            int br = idx >> 3, bc = (idx & 7) * 8;      // B: 32 k-rows x 64 n
            *(uint4*)(sBh + br * BNP + bc) =
                *(const uint4*)(Wh + (size_t)(k0 + br) * N + n0 + bc);
            *(uint4*)(sBl + br * BNP + bc) =
                *(const uint4*)(Wl + (size_t)(k0 + br) * N + n0 + bc);
        }
        __syncthreads();

        #pragma unroll
        for (int ks = 0; ks < 2; ks++) {
            int kb = ks * 16;
            uint32_t bH[4][2], bL[4][2];
            #pragma unroll
            for (int nt = 0; nt < 4; nt++) {
                uint32_t boff = (uint32_t)((kb + lb_row) * BNP + wn + nt * 8) * 2;
                ldmBt(bH[nt], sBh_b + boff);
                ldmBt(bL[nt], sBl_b + boff);
            }
            #pragma unroll
            for (int mt = 0; mt < 2; mt++) {
                uint32_t aoff = (uint32_t)((wm + mt * 16 + la_row) * AKP + kb + la_col) * 2;
                uint32_t aH[4], aL[4];
                ldmA(aH, sAh_b + aoff);
                ldmA(aL, sAl_b + aoff);
                #pragma unroll
                for (int nt = 0; nt < 4; nt++) {
                    mma16816(acc[mt][nt], aH, bH[nt]);
                    mma16816(acc[mt][nt], aH, bL[nt]);
                    mma16816(acc[mt][nt], aL, bH[nt]);
                }
            }
        }
        __syncthreads();
    }

    // Epilogue
    int g = lane >> 2, tg = lane & 3;
    #pragma unroll
    for (int mt = 0; mt < 2; mt++) {
        #pragma unroll
        for (int nt = 0; nt < 4; nt++) {
            int col = n0 + wn + nt * 8 + tg * 2;
            #pragma unroll
            for (int half = 0; half < 2; half++) {
                int row = m0 + wm + mt * 16 + g + half * 8;
                float v0 = acc[mt][nt][half * 2];
                float v1 = acc[mt][nt][half * 2 + 1];
                if (bias) { v0 += bias[col]; v1 += bias[col + 1]; }
                if (res) {
                    v0 += res[(size_t)row * ldr + col];
                    v1 += res[(size_t)row * ldr + col + 1];
                }
                if (relu) { v0 = fmaxf(v0, 0.0f); v1 = fmaxf(v1, 0.0f); }
                if (outf) {
                    outf[(size_t)row * ldo + col]     = v0;
                    outf[(size_t)row * ldo + col + 1] = v1;
                }
                if (oh) {
                    __nv_bfloat16 hi, lo;
                    bf16split(v0, &hi, &lo);
                    oh[(size_t)row * ldp + col] = hi;
                    ol[(size_t)row * ldp + col] = lo;
                    bf16split(v1, &hi, &lo);
                    oh[(size_t)row * ldp + col + 1] = hi;
                    ol[(size_t)row * ldp + col + 1] = lo;
                }
            }
        }
    }
}

// ============================================================================
// fused attention (reads g_qkv fp32, writes mha bf16 pairs + attn probs)
// grid (4, 64): blockIdx.y = b, blockIdx.x covers 16 query rows. 256 threads.
// ============================================================================
#define ATTN_SMEM_FLOATS (16384 + 16384 + 8192 + 256 + 256 + 128 + 128 + 128)
__global__ void attn_kernel(const float* __restrict__ edge,
                            const void* __restrict__ mask,
                            const float* __restrict__ be_l,
                            float* __restrict__ attn_out, int write_attn,
                            int layer)
{
    extern __shared__ float sm[];
    float* s_k   = sm;
    float* s_v   = s_k  + 16384;
    float* s_e   = s_v  + 16384;
    float* s_q   = s_e  + 8192;
    float* s_qe  = s_q  + 256;
    float* s_sc  = s_qe + 256;
    float* s_att = s_sc + 128;
    float* s_be  = s_att + 128;

    int b    = blockIdx.y;
    int i0   = blockIdx.x * 16;
    int t    = threadIdx.x;
    int lane = t & 31, w = t >> 5;
    int mode = g_mask_mode;

    for (int f4 = t; f4 < 4096; f4 += 256) {
        int d4 = f4 & 31, j = (f4 >> 5) & 63, h = f4 >> 11;
        float4 kv = *(const float4*)(g_qkv + (size_t)(b * 64 + j) * 1024 + 256 + h * 128 + d4 * 4);
        *(float4*)&s_k[h * 8192 + j * 128 + d4 * 4] = kv;
        float4 vv = *(const float4*)(g_qkv + (size_t)(b * 64 + j) * 1024 + 512 + h * 128 + d4 * 4);
        *(float4*)&s_v[h * 8192 + j * 128 + d4 * 4] = vv;
    }
    if (t < 128) s_be[t] = be_l[t];

    const float invT = 0.08838834764831843f;  // 1/sqrt(128)

    for (int ii = 0; ii < 16; ii++) {
        int i = i0 + ii;
        __syncthreads();
        const float4* esrc = (const float4*)(edge + ((size_t)(b * 64 + i)) * 64 * 128);
        for (int f4 = t; f4 < 2048; f4 += 256)
            *(float4*)&s_e[f4 * 4] = esrc[f4];
        s_q [t] = g_qkv[(size_t)(b * 64 + i) * 1024 + t];
        s_qe[t] = g_qkv[(size_t)(b * 64 + i) * 1024 + 768 + t];
        __syncthreads();

        // scores
        {
            int h = w >> 2;
            float qr[4], qer[4];
            #pragma unroll
            for (int mth = 0; mth < 4; mth++) {
                qr[mth]  = s_q [h * 128 + lane + 32 * mth];
                qer[mth] = s_qe[h * 128 + lane + 32 * mth];
            }
            float qb = 0.0f;
            #pragma unroll
            for (int mth = 0; mth < 4; mth++) qb += qr[mth] * s_be[lane + 32 * mth];
            #pragma unroll
            for (int off = 16; off; off >>= 1)
                qb += __shfl_xor_sync(0xffffffffu, qb, off);

            #pragma unroll
            for (int oo = 0; oo < 16; oo++) {
                int o = w * 16 + oo;
                int j = o & 63;
                float p = 0.0f;
                #pragma unroll
                for (int mth = 0; mth < 4; mth++) {
                    p += qr[mth]  * s_k[h * 8192 + j * 128 + lane + 32 * mth];
                    p += qer[mth] * s_e[j * 128 + lane + 32 * mth];
                }
                #pragma unroll
                for (int off = 16; off; off >>= 1)
                    p += __shfl_xor_sync(0xffffffffu, p, off);
                if (lane == 0) s_sc[o] = p + qb;
            }
        }
        __syncthreads();

        // masked softmax; faithful masked_fill(1e-10)
        if (w < 2) {
            int h = w;
            size_t mbase = ((size_t)(b * 64 + i)) * 64;
            float v0 = s_sc[h * 64 + lane]      * invT;
            float v1 = s_sc[h * 64 + lane + 32] * invT;
            if (mask_at(mask, mbase + lane,      mode)) v0 = 1e-10f;
            if (mask_at(mask, mbase + lane + 32, mode)) v1 = 1e-10f;
            float mx = fmaxf(v0, v1);
            #pragma unroll
            for (int off = 16; off; off >>= 1)
                mx = fmaxf(mx, __shfl_xor_sync(0xffffffffu, mx, off));
            float e0 = expf(v0 - mx), e1 = expf(v1 - mx);
            float s = e0 + e1;
            #pragma unroll
            for (int off = 16; off; off >>= 1)
                s += __shfl_xor_sync(0xffffffffu, s, off);
            float inv = 1.0f / s;
            e0 *= inv; e1 *= inv;
            s_att[h * 64 + lane]      = e0;
            s_att[h * 64 + lane + 32] = e1;
            if (write_attn) {
                float* ap = attn_out +
                    ((((size_t)layer * NHH + h) * BB + b) * NNODE + i) * NNODE;
                ap[lane]      = e0;
                ap[lane + 32] = e1;
            }
        }
        __syncthreads();

        // emb1 = attn@v ; ew = attn@edge; write bf16 pairs
        {
            int sel = t >> 7, h = (t >> 6) & 1, d0 = (t & 63) * 2;
            float2 acc = make_float2(0.0f, 0.0f);
            const float* base = sel ? (s_e + d0) : (s_v + h * 8192 + d0);
            #pragma unroll 8
            for (int j = 0; j < 64; j++) {
                float a = s_att[h * 64 + j];
                float2 x = *(const float2*)(base + j * 128);
                acc.x += a * x.x; acc.y += a * x.y;
            }
            size_t mo = ((size_t)(b * 64 + i)) * 512 + sel * 256 + h * 128 + d0;
            __nv_bfloat16 hi, lo;
            bf16split(acc.x, &hi, &lo); g_mhah[mo]     = hi; g_mhal[mo]     = lo;
            bf16split(acc.y, &hi, &lo); g_mhah[mo + 1] = hi; g_mhal[mo + 1] = lo;
        }
    }
}

// ---------------- final mean over nodes ----------------
__global__ void mean_kernel(float* __restrict__ out)
{
    int b = blockIdx.x, d = threadIdx.x;
    float s = 0.0f;
    for (int n = 0; n < 64; n++) s += g_emb[(size_t)(b * 64 + n) * 128 + d];
    out[b * 128 + d] = s * (1.0f / 64.0f);
}

// ============================================================================
// host
// ============================================================================
extern "C" void kernel_launch(void* const* d_in, const int* in_sizes, int n_in,
                              void* d_out, int out_size)
{
    if (n_in < 21) return;
    bool dict = (in_sizes[3] == BB * NNODE * NNODE);

    const float *nf, *st, *ef, *Wn, *bn, *We, *be, *l1g, *l1b,
                *Wq, *Wk, *Wv, *Wo, *bo, *l2g, *l2b, *W1, *b1, *W2, *b2;
    const void* mask;

    if (dict) {
        nf  = (const float*)d_in[0];  st  = (const float*)d_in[1];
        ef  = (const float*)d_in[2];  mask = d_in[3];
        Wn  = (const float*)d_in[4];  bn  = (const float*)d_in[5];
        We  = (const float*)d_in[6];  be  = (const float*)d_in[7];
        l1g = (const float*)d_in[8];  l1b = (const float*)d_in[9];
        Wq  = (const float*)d_in[10]; Wk  = (const float*)d_in[11];
        Wv  = (const float*)d_in[12]; Wo  = (const float*)d_in[13];
        bo  = (const float*)d_in[14]; l2g = (const float*)d_in[15];
        l2b = (const float*)d_in[16]; W1  = (const float*)d_in[17];
        b1  = (const float*)d_in[18]; W2  = (const float*)d_in[19];
        b2  = (const float*)d_in[20];
    } else {
        nf  = (const float*)d_in[0];  st  = (const float*)d_in[1];
        ef  = (const float*)d_in[2];
        Wn  = (const float*)d_in[3];  bn  = (const float*)d_in[4];
        We  = (const float*)d_in[5];  be  = (const float*)d_in[6];
        l1g = (const float*)d_in[7];  l1b = (const float*)d_in[8];
        Wq  = (const float*)d_in[9];  Wk  = (const float*)d_in[10];
        Wv  = (const float*)d_in[11]; Wo  = (const float*)d_in[12];
        bo  = (const float*)d_in[13]; l2g = (const float*)d_in[14];
        l2b = (const float*)d_in[15]; W1  = (const float*)d_in[16];
        b1  = (const float*)d_in[17]; W2  = (const float*)d_in[18];
        b2  = (const float*)d_in[19]; mask = d_in[20];
    }

    float *p_emb, *p_cvec, *p_qkv;
    __nv_bfloat16 *p_x0h, *p_x0l, *p_hh, *p_hl, *p_mhah, *p_mhal, *p_ffh, *p_ffl;
    __nv_bfloat16 *p_WnImg, *p_WprojImg, *p_WbigImg, *p_W1Img, *p_W2Img;
    cudaGetSymbolAddress((void**)&p_emb,   g_emb);
    cudaGetSymbolAddress((void**)&p_cvec,  g_cvec);
    cudaGetSymbolAddress((void**)&p_x0h,   g_x0h);
    cudaGetSymbolAddress((void**)&p_x0l,   g_x0l);
    cudaGetSymbolAddress((void**)&p_hh,    g_hh);
    cudaGetSymbolAddress((void**)&p_hl,    g_hl);
    cudaGetSymbolAddress((void**)&p_mhah,  g_mhah);
    cudaGetSymbolAddress((void**)&p_mhal,  g_mhal);
    cudaGetSymbolAddress((void**)&p_ffh,   g_ffh);
    cudaGetSymbolAddress((void**)&p_ffl,   g_ffl);
    cudaGetSymbolAddress((void**)&p_qkv,   g_qkv);
    cudaGetSymbolAddress((void**)&p_WnImg,   g_WnImg);
    cudaGetSymbolAddress((void**)&p_WprojImg, g_WprojImg);
    cudaGetSymbolAddress((void**)&p_WbigImg,  g_WbigImg);
    cudaGetSymbolAddress((void**)&p_W1Img,    g_W1Img);
    cudaGetSymbolAddress((void**)&p_W2Img,    g_W2Img);

    const int ATTN_SMEM = ATTN_SMEM_FLOATS * 4;
    cudaFuncSetAttribute(attn_kernel, cudaFuncAttributeMaxDynamicSharedMemorySize, ATTN_SMEM);

    float* out = (float*)d_out;
    size_t need_attn = (size_t)BB * DD + (size_t)LLAYERS * NHH * BB * NNODE * NNODE;
    int write_attn = ((size_t)out_size >= need_attn) ? 1 : 0;
    float* attn_base = out + BB * DD;

    detect_mask_kernel<<<1, 256>>>((const unsigned char*)mask);
    concat_kernel<<<(ROWS * 64 + 255) / 256, 256>>>(nf, st);

    // weight prep (activation-independent, all coalesced)
    wn_prep<<<128, 256>>>(Wn);
    wqkv_prep<<<dim3(384, 1, LLAYERS), 256>>>(Wq, Wk, Wv);
    wqe_prep<<<dim3(8, 8, 2 * LLAYERS), dim3(16, 16)>>>(Wq, We);
    wo_prep<<<dim3(128, 1, LLAYERS), 256>>>(Wo);
    wbigc_prep<<<dim3(8, 8, 2 * LLAYERS), dim3(16, 16)>>>(We, Wo);
    w1_prep<<<dim3(256, 1, LLAYERS), 256>>>(W1);
    w2_prep<<<dim3(256, 1, LLAYERS), 256>>>(W2);
    cvec_kernel<<<LLAYERS, 128>>>(be, bo, Wo);

    // emb = cat(node, stpe) @ Wn + bn
    mm_mma<<<dim3(2, 64), 128>>>(p_x0h, p_x0l, p_WnImg, 128, 256,
        bn, nullptr, 0, p_emb, 128, nullptr, nullptr, 0, 0);

    for (int l = 0; l < LLAYERS; l++) {
        const float* be_l = be + (size_t)l * 128;
        // pre-LN + fused q|k|v|qe projection (N=1024)
        ln_kernel<<<512, 256>>>(p_emb, l1g + l * 128, l1b + l * 128, 1e-5f);
        mm_mma<<<dim3(16, 64), 128>>>(p_hh, p_hl,
            p_WprojImg + (size_t)l * 2 * 128 * 1024, 1024, 128,
            nullptr, nullptr, 0, p_qkv, 1024, nullptr, nullptr, 0, 0);

        // fused attention
        attn_kernel<<<dim3(4, BB), 256, ATTN_SMEM>>>(ef, mask, be_l,
                                                     attn_base, write_attn, l);

        // emb = mha @ Wbig + cvec + residual
        mm_mma<<<dim3(2, 64), 128>>>(p_mhah, p_mhal,
            p_WbigImg + (size_t)l * 2 * 512 * 128, 128, 512,
            p_cvec + l * 128, p_emb, 128, p_emb, 128, nullptr, nullptr, 0, 0);

        // FFN
        ln_kernel<<<512, 256>>>(p_emb, l2g + l * 128, l2b + l * 128, 1e-6f);
        mm_mma<<<dim3(8, 64), 128>>>(p_hh, p_hl,
            p_W1Img + (size_t)l * 2 * 128 * 512, 512, 128,
            b1 + (size_t)l * 512, nullptr, 0, nullptr, 0, p_ffh, p_ffl, 512, 1);
        mm_mma<<<dim3(2, 64), 128>>>(p_ffh, p_ffl,
            p_W2Img + (size_t)l * 2 * 512 * 128, 128, 512,
            b2 + (size_t)l * 128, p_emb, 128, p_emb, 128, nullptr, nullptr, 0, 0);
    }

    mean_kernel<<<BB, 128>>>(out);
}

// round 6
// speedup vs baseline: 1.9752x; 1.6009x over previous
#include <cuda_runtime.h>
#include <cuda_bf16.h>
#include <math.h>
#include <stdint.h>

// Problem dims
#define BB 64
#define NNODE 64
#define DD 128
#define NHH 2
#define LLAYERS 2
#define ROWS (BB*NNODE)          // 4096

// ============================================================================
// Helpers
// ============================================================================
__device__ __forceinline__ uint32_t smem_u32(const void* p) {
    uint32_t a;
    asm("{ .reg .u64 t; cvta.to.shared.u64 t, %1; cvt.u32.u64 %0, t; }"
        : "=r"(a) : "l"(p));
    return a;
}

__device__ __forceinline__ void ldmA(uint32_t* a, uint32_t addr) {
    asm volatile("ldmatrix.sync.aligned.m8n8.x4.shared.b16 {%0,%1,%2,%3}, [%4];"
        : "=r"(a[0]), "=r"(a[1]), "=r"(a[2]), "=r"(a[3]) : "r"(addr));
}
__device__ __forceinline__ void ldmBt(uint32_t* b, uint32_t addr) {
    asm volatile("ldmatrix.sync.aligned.m8n8.x2.trans.shared.b16 {%0,%1}, [%2];"
        : "=r"(b[0]), "=r"(b[1]) : "r"(addr));
}
__device__ __forceinline__ void mma16816(float* d, const uint32_t* a, const uint32_t* b) {
    asm volatile("mma.sync.aligned.m16n8k16.row.col.f32.bf16.bf16.f32 "
        "{%0,%1,%2,%3}, {%4,%5,%6,%7}, {%8,%9}, {%0,%1,%2,%3};"
        : "+f"(d[0]), "+f"(d[1]), "+f"(d[2]), "+f"(d[3])
        : "r"(a[0]), "r"(a[1]), "r"(a[2]), "r"(a[3]), "r"(b[0]), "r"(b[1]));
}

__device__ __forceinline__ void bf16split(float v, __nv_bfloat16* hi, __nv_bfloat16* lo) {
    __nv_bfloat16 h = __float2bfloat16(v);
    *hi = h;
    *lo = __float2bfloat16(v - __bfloat162float(h));
}

// ============================================================================
// Scratch (device globals; no allocation)
// ============================================================================
__device__ __nv_bfloat16 g_x0h [ROWS*256];
__device__ __nv_bfloat16 g_x0l [ROWS*256];
__device__ float         g_emb [ROWS*128];
__device__ __nv_bfloat16 g_hh  [ROWS*128];
__device__ __nv_bfloat16 g_hl  [ROWS*128];
__device__ float         g_qkv [ROWS*1024];
__device__ __nv_bfloat16 g_mhah[ROWS*512];
__device__ __nv_bfloat16 g_mhal[ROWS*512];
__device__ __nv_bfloat16 g_ffh [ROWS*512];
__device__ __nv_bfloat16 g_ffl [ROWS*512];
__device__ float         g_cvec[LLAYERS*128];
__device__ int           g_mask_mode;

// Weight images, natural [K][N] bf16, hi plane then lo plane
__device__ __nv_bfloat16 g_WnImg  [2*256*128];
__device__ __nv_bfloat16 g_WprojImg[LLAYERS][2*128*1024];
__device__ __nv_bfloat16 g_WbigImg [LLAYERS][2*512*128];
__device__ __nv_bfloat16 g_W1Img   [LLAYERS][2*128*512];
__device__ __nv_bfloat16 g_W2Img   [LLAYERS][2*512*128];

// ============================================================================
// mask dtype detection (parallel)
// ============================================================================
__global__ void detect_mask_kernel(const unsigned char* __restrict__ m)
{
    __shared__ int cnt[2];
    if (threadIdx.x < 2) cnt[threadIdx.x] = 0;
    __syncthreads();
    int u8 = 0, f32 = 0;
    for (int i = threadIdx.x; i < 4096; i += 256) {
        unsigned char v = m[i];
        if (v) {
            int r = i & 3;
            if (r == 1) u8++;
            else if (r == 3) f32++;
        }
    }
    if (u8)  atomicAdd(&cnt[0], u8);
    if (f32) atomicAdd(&cnt[1], f32);
    __syncthreads();
    if (threadIdx.x == 0)
        g_mask_mode = cnt[0] ? 0 : (cnt[1] ? 2 : 1);
}
__device__ __forceinline__ bool mask_at(const void* mp, size_t idx, int mode)
{
    if (mode == 0) return ((const unsigned char*)mp)[idx] != 0;
    if (mode == 1) return ((const int*)mp)[idx] != 0;
    return ((const float*)mp)[idx] != 0.0f;
}

// ============================================================================
// Prologue: weight image prep — natural [K][N], coalesced convert-copy
// ============================================================================
__global__ void wn_prep(const float* __restrict__ Wn)
{
    int t = blockIdx.x * 256 + threadIdx.x;
    if (t >= 256 * 128) return;
    __nv_bfloat16 hi, lo; bf16split(Wn[t], &hi, &lo);
    g_WnImg[t] = hi; g_WnImg[32768 + t] = lo;
}

__global__ void wqkv_prep(const float* __restrict__ Wq, const float* __restrict__ Wk,
                          const float* __restrict__ Wv)
{
    int l = blockIdx.z;
    int t = blockIdx.x * 256 + threadIdx.x;
    if (t >= 128 * 768) return;
    int k = t / 768, n = t % 768;
    const float* W = (n < 256) ? Wq : (n < 512 ? Wk : Wv);
    float v = W[(size_t)l * 128 * 256 + (size_t)k * 256 + (n & 255)];
    __nv_bfloat16 hi, lo; bf16split(v, &hi, &lo);
    g_WprojImg[l][(size_t)k * 1024 + n]          = hi;
    g_WprojImg[l][131072 + (size_t)k * 1024 + n] = lo;
}

__global__ void wqe_prep(const float* __restrict__ Wq, const float* __restrict__ We)
{
    int l = blockIdx.z >> 1, h = blockIdx.z & 1;
    int e = blockIdx.x * 16 + threadIdx.x;
    int d = blockIdx.y * 16 + threadIdx.y;
    const float* wq = Wq + (size_t)l * 128 * 256 + (size_t)d * 256 + h * 128;
    const float* we = We + (size_t)l * 128 * 128 + (size_t)e * 128;
    float acc = 0.0f;
    #pragma unroll 8
    for (int c = 0; c < 128; c++) acc += wq[c] * we[c];
    size_t o = (size_t)d * 1024 + 768 + h * 128 + e;
    __nv_bfloat16 hi, lo; bf16split(acc, &hi, &lo);
    g_WprojImg[l][o] = hi; g_WprojImg[l][131072 + o] = lo;
}

__global__ void wo_prep(const float* __restrict__ Wo)
{
    int l = blockIdx.z;
    int t = blockIdx.x * 256 + threadIdx.x;
    if (t >= 256 * 128) return;
    __nv_bfloat16 hi, lo; bf16split(Wo[(size_t)l * 32768 + t], &hi, &lo);
    g_WbigImg[l][t] = hi; g_WbigImg[l][65536 + t] = lo;
}

__global__ void wbigc_prep(const float* __restrict__ We, const float* __restrict__ Wo)
{
    int l = blockIdx.z >> 1, h = blockIdx.z & 1;
    int n = blockIdx.x * 16 + threadIdx.x;
    int f = blockIdx.y * 16 + threadIdx.y;
    const float* we = We + (size_t)l * 128 * 128 + (size_t)f * 128;
    const float* wo = Wo + (size_t)l * 256 * 128 + (size_t)(h * 128) * 128 + n;
    float acc = 0.0f;
    #pragma unroll 8
    for (int e = 0; e < 128; e++) acc += we[e] * wo[(size_t)e * 128];
    size_t o = (size_t)(256 + h * 128 + f) * 128 + n;
    __nv_bfloat16 hi, lo; bf16split(acc, &hi, &lo);
    g_WbigImg[l][o] = hi; g_WbigImg[l][65536 + o] = lo;
}

__global__ void w1_prep(const float* __restrict__ W1)
{
    int l = blockIdx.z;
    int t = blockIdx.x * 256 + threadIdx.x;
    if (t >= 128 * 512) return;
    __nv_bfloat16 hi, lo; bf16split(W1[(size_t)l * 65536 + t], &hi, &lo);
    g_W1Img[l][t] = hi; g_W1Img[l][65536 + t] = lo;
}

__global__ void w2_prep(const float* __restrict__ W2)
{
    int l = blockIdx.z;
    int t = blockIdx.x * 256 + threadIdx.x;
    if (t >= 512 * 128) return;
    __nv_bfloat16 hi, lo; bf16split(W2[(size_t)l * 65536 + t], &hi, &lo);
    g_W2Img[l][t] = hi; g_W2Img[l][65536 + t] = lo;
}

__global__ void cvec_kernel(const float* __restrict__ be,
                            const float* __restrict__ bo,
                            const float* __restrict__ Wo)
{
    int l = blockIdx.x, d = threadIdx.x;
    float acc = bo[l * 128 + d];
    const float* wo = Wo + (size_t)l * 256 * 128;
    const float* bel = be + l * 128;
    for (int r = 0; r < 256; r++) acc += bel[r & 127] * wo[(size_t)r * 128 + d];
    g_cvec[l * 128 + d] = acc;
}

// ============================================================================
// concat(node_feat, stpe) -> bf16 pairs [4096,256]
// ============================================================================
__global__ void concat_kernel(const float* __restrict__ nf, const float* __restrict__ st)
{
    int t = blockIdx.x * blockDim.x + threadIdx.x;
    if (t < ROWS * 64) {
        int row = t >> 6, c4 = t & 63;
        float4 val = (c4 < 32) ? ((const float4*)nf)[row * 32 + c4]
                               : ((const float4*)st)[row * 32 + (c4 - 32)];
        size_t o = (size_t)row * 256 + c4 * 4;
        float vv[4] = {val.x, val.y, val.z, val.w};
        #pragma unroll
        for (int j = 0; j < 4; j++) {
            __nv_bfloat16 hi, lo; bf16split(vv[j], &hi, &lo);
            g_x0h[o + j] = hi; g_x0l[o + j] = lo;
        }
    }
}

// ============================================================================
// LayerNorm -> bf16 pairs
// ============================================================================
__global__ void ln_kernel(const float* __restrict__ x,
                          const float* __restrict__ g, const float* __restrict__ b,
                          float eps)
{
    int row  = blockIdx.x * 8 + (threadIdx.x >> 5);
    int lane = threadIdx.x & 31;
    const float* xr = x + (size_t)row * 128;
    float v0 = xr[lane], v1 = xr[lane + 32], v2 = xr[lane + 64], v3 = xr[lane + 96];
    float s = v0 + v1 + v2 + v3;
    #pragma unroll
    for (int o = 16; o; o >>= 1) s += __shfl_xor_sync(0xffffffffu, s, o);
    float mu = s * (1.0f / 128.0f);
    float d0 = v0 - mu, d1 = v1 - mu, d2 = v2 - mu, d3 = v3 - mu;
    float q = d0*d0 + d1*d1 + d2*d2 + d3*d3;
    #pragma unroll
    for (int o = 16; o; o >>= 1) q += __shfl_xor_sync(0xffffffffu, q, o);
    float inv = rsqrtf(q * (1.0f / 128.0f) + eps);
    size_t base = (size_t)row * 128;
    float y0 = d0 * inv * g[lane]      + b[lane];
    float y1 = d1 * inv * g[lane + 32] + b[lane + 32];
    float y2 = d2 * inv * g[lane + 64] + b[lane + 64];
    float y3 = d3 * inv * g[lane + 96] + b[lane + 96];
    __nv_bfloat16 hi, lo;
    bf16split(y0, &hi, &lo); g_hh[base + lane]      = hi; g_hl[base + lane]      = lo;
    bf16split(y1, &hi, &lo); g_hh[base + lane + 32] = hi; g_hl[base + lane + 32] = lo;
    bf16split(y2, &hi, &lo); g_hh[base + lane + 64] = hi; g_hl[base + lane + 64] = lo;
    bf16split(y3, &hi, &lo); g_hh[base + lane + 96] = hi; g_hl[base + lane + 96] = lo;
}

// ============================================================================
// mma.sync GEMM (unchanged from R5): 64x64 tile, 128 threads, hi/lo split
// ============================================================================
#define AKP 40
#define BNP 72
__global__ __launch_bounds__(128) void mm_mma(
    const __nv_bfloat16* __restrict__ Ah, const __nv_bfloat16* __restrict__ Al,
    const __nv_bfloat16* __restrict__ Wimg, int N, int K,
    const float* __restrict__ bias,
    const float* __restrict__ res, int ldr,
    float* __restrict__ outf, int ldo,
    __nv_bfloat16* __restrict__ oh, __nv_bfloat16* __restrict__ ol, int ldp,
    int relu)
{
    __shared__ __nv_bfloat16 sAh[64 * AKP];
    __shared__ __nv_bfloat16 sAl[64 * AKP];
    __shared__ __nv_bfloat16 sBh[32 * BNP];
    __shared__ __nv_bfloat16 sBl[32 * BNP];

    int tid = threadIdx.x, lane = tid & 31, wid = tid >> 5;
    int m0 = blockIdx.y * 64, n0 = blockIdx.x * 64;
    int wm = (wid >> 1) * 32, wn = (wid & 1) * 32;

    const __nv_bfloat16* Wh = Wimg;
    const __nv_bfloat16* Wl = Wimg + (size_t)N * K;

    float acc[2][4][4];
    #pragma unroll
    for (int mt = 0; mt < 2; mt++)
        #pragma unroll
        for (int nt = 0; nt < 4; nt++)
            #pragma unroll
            for (int c = 0; c < 4; c++) acc[mt][nt][c] = 0.0f;

    uint32_t sAh_b = smem_u32(sAh), sAl_b = smem_u32(sAl);
    uint32_t sBh_b = smem_u32(sBh), sBl_b = smem_u32(sBl);

    int la_row = lane & 15, la_col = (lane >> 4) * 8;
    int lb_row = lane & 15;

    for (int k0 = 0; k0 < K; k0 += 32) {
        #pragma unroll
        for (int i = 0; i < 2; i++) {
            int idx = tid + i * 128;
            int ar = idx >> 2, ac = (idx & 3) * 8;
            *(uint4*)(sAh + ar * AKP + ac) =
                *(const uint4*)(Ah + (size_t)(m0 + ar) * K + k0 + ac);
            *(uint4*)(sAl + ar * AKP + ac) =
                *(const uint4*)(Al + (size_t)(m0 + ar) * K + k0 + ac);
            int br = idx >> 3, bc = (idx & 7) * 8;
            *(uint4*)(sBh + br * BNP + bc) =
                *(const uint4*)(Wh + (size_t)(k0 + br) * N + n0 + bc);
            *(uint4*)(sBl + br * BNP + bc) =
                *(const uint4*)(Wl + (size_t)(k0 + br) * N + n0 + bc);
        }
        __syncthreads();

        #pragma unroll
        for (int ks = 0; ks < 2; ks++) {
            int kb = ks * 16;
            uint32_t bH[4][2], bL[4][2];
            #pragma unroll
            for (int nt = 0; nt < 4; nt++) {
                uint32_t boff = (uint32_t)((kb + lb_row) * BNP + wn + nt * 8) * 2;
                ldmBt(bH[nt], sBh_b + boff);
                ldmBt(bL[nt], sBl_b + boff);
            }
            #pragma unroll
            for (int mt = 0; mt < 2; mt++) {
                uint32_t aoff = (uint32_t)((wm + mt * 16 + la_row) * AKP + kb + la_col) * 2;
                uint32_t aH[4], aL[4];
                ldmA(aH, sAh_b + aoff);
                ldmA(aL, sAl_b + aoff);
                #pragma unroll
                for (int nt = 0; nt < 4; nt++) {
                    mma16816(acc[mt][nt], aH, bH[nt]);
                    mma16816(acc[mt][nt], aH, bL[nt]);
                    mma16816(acc[mt][nt], aL, bH[nt]);
                }
            }
        }
        __syncthreads();
    }

    int g = lane >> 2, tg = lane & 3;
    #pragma unroll
    for (int mt = 0; mt < 2; mt++) {
        #pragma unroll
        for (int nt = 0; nt < 4; nt++) {
            int col = n0 + wn + nt * 8 + tg * 2;
            #pragma unroll
            for (int half = 0; half < 2; half++) {
                int row = m0 + wm + mt * 16 + g + half * 8;
                float v0 = acc[mt][nt][half * 2];
                float v1 = acc[mt][nt][half * 2 + 1];
                if (bias) { v0 += bias[col]; v1 += bias[col + 1]; }
                if (res) {
                    v0 += res[(size_t)row * ldr + col];
                    v1 += res[(size_t)row * ldr + col + 1];
                }
                if (relu) { v0 = fmaxf(v0, 0.0f); v1 = fmaxf(v1, 0.0f); }
                if (outf) {
                    outf[(size_t)row * ldo + col]     = v0;
                    outf[(size_t)row * ldo + col + 1] = v1;
                }
                if (oh) {
                    __nv_bfloat16 hi, lo;
                    bf16split(v0, &hi, &lo);
                    oh[(size_t)row * ldp + col] = hi;
                    ol[(size_t)row * ldp + col] = lo;
                    bf16split(v1, &hi, &lo);
                    oh[(size_t)row * ldp + col + 1] = hi;
                    ol[(size_t)row * ldp + col + 1] = lo;
                }
            }
        }
    }
}

// ============================================================================
// fused attention v2 — one block per (b, i); 256 threads; no serial row loop.
// grid (64, 64): blockIdx.x = i, blockIdx.y = b.
// smem: edge tile 32KB + partial sums 16KB + vectors (~52KB) -> 4 CTAs/SM.
// k,v streamed from gmem (L2-resident).
// ============================================================================
#define ATTN_SMEM_FLOATS (8192 + 4096 + 256 + 256 + 128 + 128 + 128)
__global__ __launch_bounds__(256) void attn_kernel(
    const float* __restrict__ edge,
    const void* __restrict__ mask,
    const float* __restrict__ be_l,
    float* __restrict__ attn_out, int write_attn,
    int layer)
{
    extern __shared__ float sm[];
    float* s_e    = sm;              // 8192: edge[64][128]
    float* s_part = s_e + 8192;      // 4096: partials [8 warps][512]
    float* s_q    = s_part + 4096;   // 256
    float* s_qe   = s_q + 256;       // 256
    float* s_sc   = s_qe + 256;      // 128
    float* s_att  = s_sc + 128;      // 128
    float* s_be   = s_att + 128;     // 128

    int b = blockIdx.y, i = blockIdx.x;
    int t = threadIdx.x, lane = t & 31, w = t >> 5;
    int mode = g_mask_mode;
    size_t qrow = (size_t)(b * 64 + i) * 1024;

    // stage edge tile + q/qe/be
    const float4* esrc = (const float4*)(edge + ((size_t)(b * 64 + i)) * 8192);
    #pragma unroll
    for (int r = 0; r < 8; r++)
        *(float4*)&s_e[(t + r * 256) * 4] = esrc[t + r * 256];
    s_q [t] = g_qkv[qrow + t];
    s_qe[t] = g_qkv[qrow + 768 + t];
    if (t < 128) s_be[t] = be_l[t];
    __syncthreads();

    // scores: warp w -> pairs p in [w*16, w*16+16), h = w>>2 fixed per warp
    {
        int h = w >> 2;
        float4 q4  = *(float4*)&s_q [h * 128 + lane * 4];
        float4 qe4 = *(float4*)&s_qe[h * 128 + lane * 4];
        float4 be4 = *(float4*)&s_be[lane * 4];
        float qb = q4.x*be4.x + q4.y*be4.y + q4.z*be4.z + q4.w*be4.w;
        #pragma unroll
        for (int off = 16; off; off >>= 1)
            qb += __shfl_xor_sync(0xffffffffu, qb, off);

        #pragma unroll
        for (int oo = 0; oo < 16; oo++) {
            int p = w * 16 + oo;
            int j = p & 63;
            float4 k4 = *(const float4*)(g_qkv + (size_t)(b * 64 + j) * 1024
                                         + 256 + h * 128 + lane * 4);
            float4 e4 = *(float4*)&s_e[j * 128 + lane * 4];
            float d = q4.x*k4.x + q4.y*k4.y + q4.z*k4.z + q4.w*k4.w
                    + qe4.x*e4.x + qe4.y*e4.y + qe4.z*e4.z + qe4.w*e4.w;
            #pragma unroll
            for (int off = 16; off; off >>= 1)
                d += __shfl_xor_sync(0xffffffffu, d, off);
            if (lane == 0) s_sc[p] = d + qb;
        }
    }
    __syncthreads();

    // masked softmax (warps 0,1 = heads 0,1); faithful masked_fill(1e-10)
    if (w < 2) {
        const float invT = 0.08838834764831843f;  // 1/sqrt(128)
        int h = w;
        size_t mbase = ((size_t)(b * 64 + i)) * 64;
        float v0 = s_sc[h * 64 + lane]      * invT;
        float v1 = s_sc[h * 64 + lane + 32] * invT;
        if (mask_at(mask, mbase + lane,      mode)) v0 = 1e-10f;
        if (mask_at(mask, mbase + lane + 32, mode)) v1 = 1e-10f;
        float mx = fmaxf(v0, v1);
        #pragma unroll
        for (int off = 16; off; off >>= 1)
            mx = fmaxf(mx, __shfl_xor_sync(0xffffffffu, mx, off));
        float e0 = expf(v0 - mx), e1 = expf(v1 - mx);
        float s = e0 + e1;
        #pragma unroll
        for (int off = 16; off; off >>= 1)
            s += __shfl_xor_sync(0xffffffffu, s, off);
        float inv = 1.0f / s;
        e0 *= inv; e1 *= inv;
        s_att[h * 64 + lane]      = e0;
        s_att[h * 64 + lane + 32] = e1;
        if (write_attn) {
            float* ap = attn_out +
                ((((size_t)layer * NHH + h) * BB + b) * NNODE + i) * NNODE;
            ap[lane]      = e0;
            ap[lane + 32] = e1;
        }
    }
    __syncthreads();

    // AV: warp w handles j = w + jj*8; coalesced v reads; partials in smem
    {
        float av0[4] = {}, av1[4] = {}, ae0[4] = {}, ae1[4] = {};
        #pragma unroll
        for (int jj = 0; jj < 8; jj++) {
            int j = w + jj * 8;
            const float* vrow = g_qkv + (size_t)(b * 64 + j) * 1024 + 512;
            float4 v0 = *(const float4*)(vrow + lane * 4);
            float4 v1 = *(const float4*)(vrow + 128 + lane * 4);
            float4 e4 = *(float4*)&s_e[j * 128 + lane * 4];
            float a0 = s_att[j], a1 = s_att[64 + j];
            av0[0] += a0 * v0.x; av0[1] += a0 * v0.y; av0[2] += a0 * v0.z; av0[3] += a0 * v0.w;
            av1[0] += a1 * v1.x; av1[1] += a1 * v1.y; av1[2] += a1 * v1.z; av1[3] += a1 * v1.w;
            ae0[0] += a0 * e4.x; ae0[1] += a0 * e4.y; ae0[2] += a0 * e4.z; ae0[3] += a0 * e4.w;
            ae1[0] += a1 * e4.x; ae1[1] += a1 * e4.y; ae1[2] += a1 * e4.z; ae1[3] += a1 * e4.w;
        }
        float* pw = s_part + w * 512;
        *(float4*)&pw[lane * 4]             = make_float4(av0[0], av0[1], av0[2], av0[3]);
        *(float4*)&pw[128 + lane * 4]       = make_float4(av1[0], av1[1], av1[2], av1[3]);
        *(float4*)&pw[256 + lane * 4]       = make_float4(ae0[0], ae0[1], ae0[2], ae0[3]);
        *(float4*)&pw[256 + 128 + lane * 4] = make_float4(ae1[0], ae1[1], ae1[2], ae1[3]);
    }
    __syncthreads();

    // reduce across 8 warps and emit bf16 pairs
    #pragma unroll
    for (int rep = 0; rep < 2; rep++) {
        int o = t + rep * 256;
        float s = 0.0f;
        #pragma unroll
        for (int ww = 0; ww < 8; ww++) s += s_part[ww * 512 + o];
        size_t mo = ((size_t)(b * 64 + i)) * 512 + o;
        __nv_bfloat16 hi, lo; bf16split(s, &hi, &lo);
        g_mhah[mo] = hi; g_mhal[mo] = lo;
    }
}

// ---------------- final mean over nodes ----------------
__global__ void mean_kernel(float* __restrict__ out)
{
    int b = blockIdx.x, d = threadIdx.x;
    float s = 0.0f;
    for (int n = 0; n < 64; n++) s += g_emb[(size_t)(b * 64 + n) * 128 + d];
    out[b * 128 + d] = s * (1.0f / 64.0f);
}

// ============================================================================
// host
// ============================================================================
extern "C" void kernel_launch(void* const* d_in, const int* in_sizes, int n_in,
                              void* d_out, int out_size)
{
    if (n_in < 21) return;
    bool dict = (in_sizes[3] == BB * NNODE * NNODE);

    const float *nf, *st, *ef, *Wn, *bn, *We, *be, *l1g, *l1b,
                *Wq, *Wk, *Wv, *Wo, *bo, *l2g, *l2b, *W1, *b1, *W2, *b2;
    const void* mask;

    if (dict) {
        nf  = (const float*)d_in[0];  st  = (const float*)d_in[1];
        ef  = (const float*)d_in[2];  mask = d_in[3];
        Wn  = (const float*)d_in[4];  bn  = (const float*)d_in[5];
        We  = (const float*)d_in[6];  be  = (const float*)d_in[7];
        l1g = (const float*)d_in[8];  l1b = (const float*)d_in[9];
        Wq  = (const float*)d_in[10]; Wk  = (const float*)d_in[11];
        Wv  = (const float*)d_in[12]; Wo  = (const float*)d_in[13];
        bo  = (const float*)d_in[14]; l2g = (const float*)d_in[15];
        l2b = (const float*)d_in[16]; W1  = (const float*)d_in[17];
        b1  = (const float*)d_in[18]; W2  = (const float*)d_in[19];
        b2  = (const float*)d_in[20];
    } else {
        nf  = (const float*)d_in[0];  st  = (const float*)d_in[1];
        ef  = (const float*)d_in[2];
        Wn  = (const float*)d_in[3];  bn  = (const float*)d_in[4];
        We  = (const float*)d_in[5];  be  = (const float*)d_in[6];
        l1g = (const float*)d_in[7];  l1b = (const float*)d_in[8];
        Wq  = (const float*)d_in[9];  Wk  = (const float*)d_in[10];
        Wv  = (const float*)d_in[11]; Wo  = (const float*)d_in[12];
        bo  = (const float*)d_in[13]; l2g = (const float*)d_in[14];
        l2b = (const float*)d_in[15]; W1  = (const float*)d_in[16];
        b1  = (const float*)d_in[17]; W2  = (const float*)d_in[18];
        b2  = (const float*)d_in[19]; mask = d_in[20];
    }

    float *p_emb, *p_cvec, *p_qkv;
    __nv_bfloat16 *p_x0h, *p_x0l, *p_hh, *p_hl, *p_mhah, *p_mhal, *p_ffh, *p_ffl;
    __nv_bfloat16 *p_WnImg, *p_WprojImg, *p_WbigImg, *p_W1Img, *p_W2Img;
    cudaGetSymbolAddress((void**)&p_emb,   g_emb);
    cudaGetSymbolAddress((void**)&p_cvec,  g_cvec);
    cudaGetSymbolAddress((void**)&p_x0h,   g_x0h);
    cudaGetSymbolAddress((void**)&p_x0l,   g_x0l);
    cudaGetSymbolAddress((void**)&p_hh,    g_hh);
    cudaGetSymbolAddress((void**)&p_hl,    g_hl);
    cudaGetSymbolAddress((void**)&p_mhah,  g_mhah);
    cudaGetSymbolAddress((void**)&p_mhal,  g_mhal);
    cudaGetSymbolAddress((void**)&p_ffh,   g_ffh);
    cudaGetSymbolAddress((void**)&p_ffl,   g_ffl);
    cudaGetSymbolAddress((void**)&p_qkv,   g_qkv);
    cudaGetSymbolAddress((void**)&p_WnImg,   g_WnImg);
    cudaGetSymbolAddress((void**)&p_WprojImg, g_WprojImg);
    cudaGetSymbolAddress((void**)&p_WbigImg,  g_WbigImg);
    cudaGetSymbolAddress((void**)&p_W1Img,    g_W1Img);
    cudaGetSymbolAddress((void**)&p_W2Img,    g_W2Img);

    const int ATTN_SMEM = ATTN_SMEM_FLOATS * 4;
    cudaFuncSetAttribute(attn_kernel, cudaFuncAttributeMaxDynamicSharedMemorySize, ATTN_SMEM);

    float* out = (float*)d_out;
    size_t need_attn = (size_t)BB * DD + (size_t)LLAYERS * NHH * BB * NNODE * NNODE;
    int write_attn = ((size_t)out_size >= need_attn) ? 1 : 0;
    float* attn_base = out + BB * DD;

    detect_mask_kernel<<<1, 256>>>((const unsigned char*)mask);
    concat_kernel<<<(ROWS * 64 + 255) / 256, 256>>>(nf, st);

    wn_prep<<<128, 256>>>(Wn);
    wqkv_prep<<<dim3(384, 1, LLAYERS), 256>>>(Wq, Wk, Wv);
    wqe_prep<<<dim3(8, 8, 2 * LLAYERS), dim3(16, 16)>>>(Wq, We);
    wo_prep<<<dim3(128, 1, LLAYERS), 256>>>(Wo);
    wbigc_prep<<<dim3(8, 8, 2 * LLAYERS), dim3(16, 16)>>>(We, Wo);
    w1_prep<<<dim3(256, 1, LLAYERS), 256>>>(W1);
    w2_prep<<<dim3(256, 1, LLAYERS), 256>>>(W2);
    cvec_kernel<<<LLAYERS, 128>>>(be, bo, Wo);

    // emb = cat(node, stpe) @ Wn + bn
    mm_mma<<<dim3(2, 64), 128>>>(p_x0h, p_x0l, p_WnImg, 128, 256,
        bn, nullptr, 0, p_emb, 128, nullptr, nullptr, 0, 0);

    for (int l = 0; l < LLAYERS; l++) {
        const float* be_l = be + (size_t)l * 128;
        ln_kernel<<<512, 256>>>(p_emb, l1g + l * 128, l1b + l * 128, 1e-5f);
        mm_mma<<<dim3(16, 64), 128>>>(p_hh, p_hl,
            p_WprojImg + (size_t)l * 2 * 128 * 1024, 1024, 128,
            nullptr, nullptr, 0, p_qkv, 1024, nullptr, nullptr, 0, 0);

        attn_kernel<<<dim3(64, 64), 256, ATTN_SMEM>>>(ef, mask, be_l,
                                                      attn_base, write_attn, l);

        mm_mma<<<dim3(2, 64), 128>>>(p_mhah, p_mhal,
            p_WbigImg + (size_t)l * 2 * 512 * 128, 128, 512,
            p_cvec + l * 128, p_emb, 128, p_emb, 128, nullptr, nullptr, 0, 0);

        ln_kernel<<<512, 256>>>(p_emb, l2g + l * 128, l2b + l * 128, 1e-6f);
        mm_mma<<<dim3(8, 64), 128>>>(p_hh, p_hl,
            p_W1Img + (size_t)l * 2 * 128 * 512, 512, 128,
            b1 + (size_t)l * 512, nullptr, 0, nullptr, 0, p_ffh, p_ffl, 512, 1);
        mm_mma<<<dim3(2, 64), 128>>>(p_ffh, p_ffl,
            p_W2Img + (size_t)l * 2 * 512 * 128, 128, 512,
            b2 + (size_t)l * 128, p_emb, 128, p_emb, 128, nullptr, nullptr, 0, 0);
    }

    mean_kernel<<<BB, 128>>>(out);
}

// round 7
// speedup vs baseline: 1.9945x; 1.0098x over previous
#include <cuda_runtime.h>
#include <cuda_bf16.h>
#include <math.h>
#include <stdint.h>

// Problem dims
#define BB 64
#define NNODE 64
#define DD 128
#define NHH 2
#define LLAYERS 2
#define ROWS (BB*NNODE)          // 4096

// ============================================================================
// Helpers
// ============================================================================
__device__ __forceinline__ uint32_t smem_u32(const void* p) {
    uint32_t a;
    asm("{ .reg .u64 t; cvta.to.shared.u64 t, %1; cvt.u32.u64 %0, t; }"
        : "=r"(a) : "l"(p));
    return a;
}

__device__ __forceinline__ void ldmA(uint32_t* a, uint32_t addr) {
    asm volatile("ldmatrix.sync.aligned.m8n8.x4.shared.b16 {%0,%1,%2,%3}, [%4];"
        : "=r"(a[0]), "=r"(a[1]), "=r"(a[2]), "=r"(a[3]) : "r"(addr));
}
__device__ __forceinline__ void ldmBt(uint32_t* b, uint32_t addr) {
    asm volatile("ldmatrix.sync.aligned.m8n8.x2.trans.shared.b16 {%0,%1}, [%2];"
        : "=r"(b[0]), "=r"(b[1]) : "r"(addr));
}
__device__ __forceinline__ void mma16816(float* d, const uint32_t* a, const uint32_t* b) {
    asm volatile("mma.sync.aligned.m16n8k16.row.col.f32.bf16.bf16.f32 "
        "{%0,%1,%2,%3}, {%4,%5,%6,%7}, {%8,%9}, {%0,%1,%2,%3};"
        : "+f"(d[0]), "+f"(d[1]), "+f"(d[2]), "+f"(d[3])
        : "r"(a[0]), "r"(a[1]), "r"(a[2]), "r"(a[3]), "r"(b[0]), "r"(b[1]));
}

__device__ __forceinline__ void bf16split(float v, __nv_bfloat16* hi, __nv_bfloat16* lo) {
    __nv_bfloat16 h = __float2bfloat16(v);
    *hi = h;
    *lo = __float2bfloat16(v - __bfloat162float(h));
}

// ============================================================================
// Scratch (device globals; no allocation)
// ============================================================================
__device__ __nv_bfloat16 g_x0h [ROWS*256];
__device__ __nv_bfloat16 g_x0l [ROWS*256];
__device__ float         g_emb [ROWS*128];
__device__ __nv_bfloat16 g_hh  [ROWS*128];
__device__ __nv_bfloat16 g_hl  [ROWS*128];
__device__ float         g_qkv [ROWS*1024];
__device__ __nv_bfloat16 g_mhah[ROWS*512];
__device__ __nv_bfloat16 g_mhal[ROWS*512];
__device__ __nv_bfloat16 g_ffh [ROWS*512];
__device__ __nv_bfloat16 g_ffl [ROWS*512];
__device__ float         g_cvec[LLAYERS*128];
__device__ int           g_mask_mode;

// Weight images, natural [K][N] bf16, hi plane then lo plane
__device__ __nv_bfloat16 g_WnImg  [2*256*128];
__device__ __nv_bfloat16 g_WprojImg[LLAYERS][2*128*1024];
__device__ __nv_bfloat16 g_WbigImg [LLAYERS][2*512*128];
__device__ __nv_bfloat16 g_W1Img   [LLAYERS][2*128*512];
__device__ __nv_bfloat16 g_W2Img   [LLAYERS][2*512*128];

// ============================================================================
// mask dtype detection (parallel)
// ============================================================================
__global__ void detect_mask_kernel(const unsigned char* __restrict__ m)
{
    __shared__ int cnt[2];
    if (threadIdx.x < 2) cnt[threadIdx.x] = 0;
    __syncthreads();
    int u8 = 0, f32 = 0;
    for (int i = threadIdx.x; i < 4096; i += 256) {
        unsigned char v = m[i];
        if (v) {
            int r = i & 3;
            if (r == 1) u8++;
            else if (r == 3) f32++;
        }
    }
    if (u8)  atomicAdd(&cnt[0], u8);
    if (f32) atomicAdd(&cnt[1], f32);
    __syncthreads();
    if (threadIdx.x == 0)
        g_mask_mode = cnt[0] ? 0 : (cnt[1] ? 2 : 1);
}
__device__ __forceinline__ bool mask_at(const void* mp, size_t idx, int mode)
{
    if (mode == 0) return ((const unsigned char*)mp)[idx] != 0;
    if (mode == 1) return ((const int*)mp)[idx] != 0;
    return ((const float*)mp)[idx] != 0.0f;
}

// ============================================================================
// Fused prologue: ALL weight-image prep in one kernel (blockIdx dispatch)
// Blocks: wn 128 | wqkv 768 | wqe 256 | wo 256 | wbigc 256 | w1 512 | w2 512 | cvec 1
// ============================================================================
#define PREP_BLOCKS (128 + 768 + 256 + 256 + 256 + 512 + 512 + 1)
__global__ void fused_prep(const float* __restrict__ Wn, const float* __restrict__ Wq,
                           const float* __restrict__ Wk, const float* __restrict__ Wv,
                           const float* __restrict__ We, const float* __restrict__ Wo,
                           const float* __restrict__ W1, const float* __restrict__ W2,
                           const float* __restrict__ be, const float* __restrict__ bo)
{
    int blk = blockIdx.x, tid = threadIdx.x;
    __nv_bfloat16 hi, lo;

    if (blk < 128) {                       // Wn [256*128] linear
        int t = blk * 256 + tid;
        bf16split(Wn[t], &hi, &lo);
        g_WnImg[t] = hi; g_WnImg[32768 + t] = lo;
        return;
    }
    blk -= 128;
    if (blk < 768) {                       // Wq/Wk/Wv -> Wproj cols 0..767
        int idx = blk * 256 + tid;         // [0, 196608)
        int l = idx / 98304, r = idx % 98304;
        int k = r / 768, n = r % 768;
        const float* W = (n < 256) ? Wq : (n < 512 ? Wk : Wv);
        float v = W[(size_t)l * 32768 + (size_t)k * 256 + (n & 255)];
        bf16split(v, &hi, &lo);
        g_WprojImg[l][(size_t)k * 1024 + n]          = hi;
        g_WprojImg[l][131072 + (size_t)k * 1024 + n] = lo;
        return;
    }
    blk -= 768;
    if (blk < 256) {                       // Wqe dots -> Wproj cols 768..1023
        int idx = blk * 256 + tid;         // [0, 65536)
        int l = idx >> 15, r = idx & 32767;
        int h = r >> 14, r2 = r & 16383;
        int e = r2 >> 7, d = r2 & 127;
        const float* wq = Wq + (size_t)l * 32768 + (size_t)d * 256 + h * 128;
        const float* we = We + (size_t)l * 16384 + (size_t)e * 128;
        float acc = 0.0f;
        #pragma unroll 8
        for (int c = 0; c < 128; c++) acc += wq[c] * we[c];
        size_t o = (size_t)d * 1024 + 768 + h * 128 + e;
        bf16split(acc, &hi, &lo);
        g_WprojImg[l][o] = hi; g_WprojImg[l][131072 + o] = lo;
        return;
    }
    blk -= 256;
    if (blk < 256) {                       // Wo -> Wbig rows 0..255
        int idx = blk * 256 + tid;         // [0, 65536)
        int l = idx >> 15, t2 = idx & 32767;
        bf16split(Wo[(size_t)l * 32768 + t2], &hi, &lo);
        g_WbigImg[l][t2] = hi; g_WbigImg[l][65536 + t2] = lo;
        return;
    }
    blk -= 256;
    if (blk < 256) {                       // We@Wo_h dots -> Wbig rows 256..511
        int idx = blk * 256 + tid;         // [0, 65536)
        int l = idx >> 15, r = idx & 32767;
        int h = r >> 14, r2 = r & 16383;
        int f = r2 >> 7, n = r2 & 127;
        const float* we = We + (size_t)l * 16384 + (size_t)f * 128;
        const float* wo = Wo + (size_t)l * 32768 + (size_t)(h * 128) * 128 + n;
        float acc = 0.0f;
        #pragma unroll 8
        for (int e = 0; e < 128; e++) acc += we[e] * wo[(size_t)e * 128];
        size_t o = (size_t)(256 + h * 128 + f) * 128 + n;
        bf16split(acc, &hi, &lo);
        g_WbigImg[l][o] = hi; g_WbigImg[l][65536 + o] = lo;
        return;
    }
    blk -= 256;
    if (blk < 512) {                       // W1
        int idx = blk * 256 + tid;         // [0, 131072)
        int l = idx >> 16, t2 = idx & 65535;
        bf16split(W1[(size_t)l * 65536 + t2], &hi, &lo);
        g_W1Img[l][t2] = hi; g_W1Img[l][65536 + t2] = lo;
        return;
    }
    blk -= 512;
    if (blk < 512) {                       // W2
        int idx = blk * 256 + tid;
        int l = idx >> 16, t2 = idx & 65535;
        bf16split(W2[(size_t)l * 65536 + t2], &hi, &lo);
        g_W2Img[l][t2] = hi; g_W2Img[l][65536 + t2] = lo;
        return;
    }
    blk -= 512;
    // cvec: one block
    {
        int l = tid >> 7, d = tid & 127;
        float acc = bo[l * 128 + d];
        const float* wo = Wo + (size_t)l * 32768;
        const float* bel = be + l * 128;
        for (int r = 0; r < 256; r++) acc += bel[r & 127] * wo[(size_t)r * 128 + d];
        g_cvec[l * 128 + d] = acc;
    }
}

// ============================================================================
// concat(node_feat, stpe) -> bf16 pairs [4096,256]
// ============================================================================
__global__ void concat_kernel(const float* __restrict__ nf, const float* __restrict__ st)
{
    int t = blockIdx.x * blockDim.x + threadIdx.x;
    if (t < ROWS * 64) {
        int row = t >> 6, c4 = t & 63;
        float4 val = (c4 < 32) ? ((const float4*)nf)[row * 32 + c4]
                               : ((const float4*)st)[row * 32 + (c4 - 32)];
        size_t o = (size_t)row * 256 + c4 * 4;
        float vv[4] = {val.x, val.y, val.z, val.w};
        #pragma unroll
        for (int j = 0; j < 4; j++) {
            __nv_bfloat16 hi, lo; bf16split(vv[j], &hi, &lo);
            g_x0h[o + j] = hi; g_x0l[o + j] = lo;
        }
    }
}

// ============================================================================
// LayerNorm -> bf16 pairs
// ============================================================================
__global__ void ln_kernel(const float* __restrict__ x,
                          const float* __restrict__ g, const float* __restrict__ b,
                          float eps)
{
    int row  = blockIdx.x * 8 + (threadIdx.x >> 5);
    int lane = threadIdx.x & 31;
    const float* xr = x + (size_t)row * 128;
    float v0 = xr[lane], v1 = xr[lane + 32], v2 = xr[lane + 64], v3 = xr[lane + 96];
    float s = v0 + v1 + v2 + v3;
    #pragma unroll
    for (int o = 16; o; o >>= 1) s += __shfl_xor_sync(0xffffffffu, s, o);
    float mu = s * (1.0f / 128.0f);
    float d0 = v0 - mu, d1 = v1 - mu, d2 = v2 - mu, d3 = v3 - mu;
    float q = d0*d0 + d1*d1 + d2*d2 + d3*d3;
    #pragma unroll
    for (int o = 16; o; o >>= 1) q += __shfl_xor_sync(0xffffffffu, q, o);
    float inv = rsqrtf(q * (1.0f / 128.0f) + eps);
    size_t base = (size_t)row * 128;
    float y0 = d0 * inv * g[lane]      + b[lane];
    float y1 = d1 * inv * g[lane + 32] + b[lane + 32];
    float y2 = d2 * inv * g[lane + 64] + b[lane + 64];
    float y3 = d3 * inv * g[lane + 96] + b[lane + 96];
    __nv_bfloat16 hi, lo;
    bf16split(y0, &hi, &lo); g_hh[base + lane]      = hi; g_hl[base + lane]      = lo;
    bf16split(y1, &hi, &lo); g_hh[base + lane + 32] = hi; g_hl[base + lane + 32] = lo;
    bf16split(y2, &hi, &lo); g_hh[base + lane + 64] = hi; g_hl[base + lane + 64] = lo;
    bf16split(y3, &hi, &lo); g_hh[base + lane + 96] = hi; g_hl[base + lane + 96] = lo;
}

// ============================================================================
// mma.sync GEMM: 64x64 tile, 128 threads, hi/lo split (unchanged)
// ============================================================================
#define AKP 40
#define BNP 72
__global__ __launch_bounds__(128) void mm_mma(
    const __nv_bfloat16* __restrict__ Ah, const __nv_bfloat16* __restrict__ Al,
    const __nv_bfloat16* __restrict__ Wimg, int N, int K,
    const float* __restrict__ bias,
    const float* __restrict__ res, int ldr,
    float* __restrict__ outf, int ldo,
    __nv_bfloat16* __restrict__ oh, __nv_bfloat16* __restrict__ ol, int ldp,
    int relu)
{
    __shared__ __nv_bfloat16 sAh[64 * AKP];
    __shared__ __nv_bfloat16 sAl[64 * AKP];
    __shared__ __nv_bfloat16 sBh[32 * BNP];
    __shared__ __nv_bfloat16 sBl[32 * BNP];

    int tid = threadIdx.x, lane = tid & 31, wid = tid >> 5;
    int m0 = blockIdx.y * 64, n0 = blockIdx.x * 64;
    int wm = (wid >> 1) * 32, wn = (wid & 1) * 32;

    const __nv_bfloat16* Wh = Wimg;
    const __nv_bfloat16* Wl = Wimg + (size_t)N * K;

    float acc[2][4][4];
    #pragma unroll
    for (int mt = 0; mt < 2; mt++)
        #pragma unroll
        for (int nt = 0; nt < 4; nt++)
            #pragma unroll
            for (int c = 0; c < 4; c++) acc[mt][nt][c] = 0.0f;

    uint32_t sAh_b = smem_u32(sAh), sAl_b = smem_u32(sAl);
    uint32_t sBh_b = smem_u32(sBh), sBl_b = smem_u32(sBl);

    int la_row = lane & 15, la_col = (lane >> 4) * 8;
    int lb_row = lane & 15;

    for (int k0 = 0; k0 < K; k0 += 32) {
        #pragma unroll
        for (int i = 0; i < 2; i++) {
            int idx = tid + i * 128;
            int ar = idx >> 2, ac = (idx & 3) * 8;
            *(uint4*)(sAh + ar * AKP + ac) =
                *(const uint4*)(Ah + (size_t)(m0 + ar) * K + k0 + ac);
            *(uint4*)(sAl + ar * AKP + ac) =
                *(const uint4*)(Al + (size_t)(m0 + ar) * K + k0 + ac);
            int br = idx >> 3, bc = (idx & 7) * 8;
            *(uint4*)(sBh + br * BNP + bc) =
                *(const uint4*)(Wh + (size_t)(k0 + br) * N + n0 + bc);
            *(uint4*)(sBl + br * BNP + bc) =
                *(const uint4*)(Wl + (size_t)(k0 + br) * N + n0 + bc);
        }
        __syncthreads();

        #pragma unroll
        for (int ks = 0; ks < 2; ks++) {
            int kb = ks * 16;
            uint32_t bH[4][2], bL[4][2];
            #pragma unroll
            for (int nt = 0; nt < 4; nt++) {
                uint32_t boff = (uint32_t)((kb + lb_row) * BNP + wn + nt * 8) * 2;
                ldmBt(bH[nt], sBh_b + boff);
                ldmBt(bL[nt], sBl_b + boff);
            }
            #pragma unroll
            for (int mt = 0; mt < 2; mt++) {
                uint32_t aoff = (uint32_t)((wm + mt * 16 + la_row) * AKP + kb + la_col) * 2;
                uint32_t aH[4], aL[4];
                ldmA(aH, sAh_b + aoff);
                ldmA(aL, sAl_b + aoff);
                #pragma unroll
                for (int nt = 0; nt < 4; nt++) {
                    mma16816(acc[mt][nt], aH, bH[nt]);
                    mma16816(acc[mt][nt], aH, bL[nt]);
                    mma16816(acc[mt][nt], aL, bH[nt]);
                }
            }
        }
        __syncthreads();
    }

    int g = lane >> 2, tg = lane & 3;
    #pragma unroll
    for (int mt = 0; mt < 2; mt++) {
        #pragma unroll
        for (int nt = 0; nt < 4; nt++) {
            int col = n0 + wn + nt * 8 + tg * 2;
            #pragma unroll
            for (int half = 0; half < 2; half++) {
                int row = m0 + wm + mt * 16 + g + half * 8;
                float v0 = acc[mt][nt][half * 2];
                float v1 = acc[mt][nt][half * 2 + 1];
                if (bias) { v0 += bias[col]; v1 += bias[col + 1]; }
                if (res) {
                    v0 += res[(size_t)row * ldr + col];
                    v1 += res[(size_t)row * ldr + col + 1];
                }
                if (relu) { v0 = fmaxf(v0, 0.0f); v1 = fmaxf(v1, 0.0f); }
                if (outf) {
                    outf[(size_t)row * ldo + col]     = v0;
                    outf[(size_t)row * ldo + col + 1] = v1;
                }
                if (oh) {
                    __nv_bfloat16 hi, lo;
                    bf16split(v0, &hi, &lo);
                    oh[(size_t)row * ldp + col] = hi;
                    ol[(size_t)row * ldp + col] = lo;
                    bf16split(v1, &hi, &lo);
                    oh[(size_t)row * ldp + col + 1] = hi;
                    ol[(size_t)row * ldp + col + 1] = lo;
                }
            }
        }
    }
}

// ============================================================================
// fused attention v3 — 2 query rows per CTA; k/v loads shared across rows.
// grid (32, 64): blockIdx.x = i-pair, blockIdx.y = b. 256 threads.
// smem ~105KB -> 2 CTAs/SM.
// ============================================================================
#define ATTN_SMEM_FLOATS (16384 + 8192 + 512 + 512 + 256 + 256 + 128)
__global__ __launch_bounds__(256) void attn_kernel(
    const float* __restrict__ edge,
    const void* __restrict__ mask,
    const float* __restrict__ be_l,
    float* __restrict__ attn_out, int write_attn,
    int layer)
{
    extern __shared__ float sm[];
    float* s_e    = sm;                 // 2 x 8192: edge tiles for i0, i1
    float* s_part = s_e + 16384;        // 8 warps x 1024 (2 i x 512)
    float* s_q    = s_part + 8192;      // 2 x 256
    float* s_qe   = s_q + 512;          // 2 x 256
    float* s_sc   = s_qe + 512;         // 2 x 128
    float* s_att  = s_sc + 256;         // 2 x 128
    float* s_be   = s_att + 256;        // 128

    int b = blockIdx.y, i0 = blockIdx.x * 2;
    int t = threadIdx.x, lane = t & 31, w = t >> 5;
    int mode = g_mask_mode;
    size_t qrow0 = (size_t)(b * 64 + i0) * 1024;

    // stage both edge tiles (contiguous 64KB) + q/qe for both i + be
    const float4* esrc = (const float4*)(edge + ((size_t)(b * 64 + i0)) * 8192);
    #pragma unroll
    for (int r = 0; r < 16; r++)
        ((float4*)s_e)[t + r * 256] = esrc[t + r * 256];
    s_q [t]       = g_qkv[qrow0 + t];
    s_q [256 + t] = g_qkv[qrow0 + 1024 + t];
    s_qe[t]       = g_qkv[qrow0 + 768 + t];
    s_qe[256 + t] = g_qkv[qrow0 + 1024 + 768 + t];
    if (t < 128) s_be[t] = be_l[t];
    __syncthreads();

    // scores: warp w: h = w>>2, j = (w&3)*16 + oo; both i per k-load
    {
        int h = w >> 2;
        float4 q0  = *(float4*)&s_q [h * 128 + lane * 4];
        float4 q1  = *(float4*)&s_q [256 + h * 128 + lane * 4];
        float4 qe0 = *(float4*)&s_qe[h * 128 + lane * 4];
        float4 qe1 = *(float4*)&s_qe[256 + h * 128 + lane * 4];
        float4 be4 = *(float4*)&s_be[lane * 4];
        float qb0 = q0.x*be4.x + q0.y*be4.y + q0.z*be4.z + q0.w*be4.w;
        float qb1 = q1.x*be4.x + q1.y*be4.y + q1.z*be4.z + q1.w*be4.w;
        #pragma unroll
        for (int off = 16; off; off >>= 1) {
            qb0 += __shfl_xor_sync(0xffffffffu, qb0, off);
            qb1 += __shfl_xor_sync(0xffffffffu, qb1, off);
        }

        #pragma unroll
        for (int oo = 0; oo < 16; oo++) {
            int j = (w & 3) * 16 + oo;
            float4 k4 = *(const float4*)(g_qkv + (size_t)(b * 64 + j) * 1024
                                         + 256 + h * 128 + lane * 4);
            float4 e0 = *(float4*)&s_e[j * 128 + lane * 4];
            float4 e1 = *(float4*)&s_e[8192 + j * 128 + lane * 4];
            float d0 = q0.x*k4.x + q0.y*k4.y + q0.z*k4.z + q0.w*k4.w
                     + qe0.x*e0.x + qe0.y*e0.y + qe0.z*e0.z + qe0.w*e0.w;
            float d1 = q1.x*k4.x + q1.y*k4.y + q1.z*k4.z + q1.w*k4.w
                     + qe1.x*e1.x + qe1.y*e1.y + qe1.z*e1.z + qe1.w*e1.w;
            #pragma unroll
            for (int off = 16; off; off >>= 1) {
                d0 += __shfl_xor_sync(0xffffffffu, d0, off);
                d1 += __shfl_xor_sync(0xffffffffu, d1, off);
            }
            if (lane == 0) {
                s_sc[h * 64 + j]       = d0 + qb0;
                s_sc[128 + h * 64 + j] = d1 + qb1;
            }
        }
    }
    __syncthreads();

    // masked softmax: warps 0..3 -> (ii = w>>1, h = w&1)
    if (w < 4) {
        const float invT = 0.08838834764831843f;  // 1/sqrt(128)
        int ii = w >> 1, h = w & 1;
        int iabs = i0 + ii;
        size_t mbase = ((size_t)(b * 64 + iabs)) * 64;
        float v0 = s_sc[ii * 128 + h * 64 + lane]      * invT;
        float v1 = s_sc[ii * 128 + h * 64 + lane + 32] * invT;
        if (mask_at(mask, mbase + lane,      mode)) v0 = 1e-10f;
        if (mask_at(mask, mbase + lane + 32, mode)) v1 = 1e-10f;
        float mx = fmaxf(v0, v1);
        #pragma unroll
        for (int off = 16; off; off >>= 1)
            mx = fmaxf(mx, __shfl_xor_sync(0xffffffffu, mx, off));
        float e0 = expf(v0 - mx), e1 = expf(v1 - mx);
        float s = e0 + e1;
        #pragma unroll
        for (int off = 16; off; off >>= 1)
            s += __shfl_xor_sync(0xffffffffu, s, off);
        float inv = 1.0f / s;
        e0 *= inv; e1 *= inv;
        s_att[ii * 128 + h * 64 + lane]      = e0;
        s_att[ii * 128 + h * 64 + lane + 32] = e1;
        if (write_attn) {
            float* ap = attn_out +
                ((((size_t)layer * NHH + h) * BB + b) * NNODE + iabs) * NNODE;
            ap[lane]      = e0;
            ap[lane + 32] = e1;
        }
    }
    __syncthreads();

    // AV: warp w: j = w + jj*8; v/edge loads shared across both i
    {
        float a0h0[4] = {}, a0h1[4] = {}, a0e0[4] = {}, a0e1[4] = {};
        float a1h0[4] = {}, a1h1[4] = {}, a1e0[4] = {}, a1e1[4] = {};
        #pragma unroll
        for (int jj = 0; jj < 8; jj++) {
            int j = w + jj * 8;
            const float* vrow = g_qkv + (size_t)(b * 64 + j) * 1024 + 512;
            float4 v0 = *(const float4*)(vrow + lane * 4);
            float4 v1 = *(const float4*)(vrow + 128 + lane * 4);
            float4 e0 = *(float4*)&s_e[j * 128 + lane * 4];
            float4 e1 = *(float4*)&s_e[8192 + j * 128 + lane * 4];
            float w00 = s_att[j],       w01 = s_att[64 + j];
            float w10 = s_att[128 + j], w11 = s_att[192 + j];
            a0h0[0] += w00*v0.x; a0h0[1] += w00*v0.y; a0h0[2] += w00*v0.z; a0h0[3] += w00*v0.w;
            a0h1[0] += w01*v1.x; a0h1[1] += w01*v1.y; a0h1[2] += w01*v1.z; a0h1[3] += w01*v1.w;
            a0e0[0] += w00*e0.x; a0e0[1] += w00*e0.y; a0e0[2] += w00*e0.z; a0e0[3] += w00*e0.w;
            a0e1[0] += w01*e0.x; a0e1[1] += w01*e0.y; a0e1[2] += w01*e0.z; a0e1[3] += w01*e0.w;
            a1h0[0] += w10*v0.x; a1h0[1] += w10*v0.y; a1h0[2] += w10*v0.z; a1h0[3] += w10*v0.w;
            a1h1[0] += w11*v1.x; a1h1[1] += w11*v1.y; a1h1[2] += w11*v1.z; a1h1[3] += w11*v1.w;
            a1e0[0] += w10*e1.x; a1e0[1] += w10*e1.y; a1e0[2] += w10*e1.z; a1e0[3] += w10*e1.w;
            a1e1[0] += w11*e1.x; a1e1[1] += w11*e1.y; a1e1[2] += w11*e1.z; a1e1[3] += w11*e1.w;
        }
        float* pw = s_part + w * 1024;
        *(float4*)&pw[lane * 4]       = make_float4(a0h0[0], a0h0[1], a0h0[2], a0h0[3]);
        *(float4*)&pw[128 + lane * 4] = make_float4(a0h1[0], a0h1[1], a0h1[2], a0h1[3]);
        *(float4*)&pw[256 + lane * 4] = make_float4(a0e0[0], a0e0[1], a0e0[2], a0e0[3]);
        *(float4*)&pw[384 + lane * 4] = make_float4(a0e1[0], a0e1[1], a0e1[2], a0e1[3]);
        *(float4*)&pw[512 + lane * 4] = make_float4(a1h0[0], a1h0[1], a1h0[2], a1h0[3]);
        *(float4*)&pw[640 + lane * 4] = make_float4(a1h1[0], a1h1[1], a1h1[2], a1h1[3]);
        *(float4*)&pw[768 + lane * 4] = make_float4(a1e0[0], a1e0[1], a1e0[2], a1e0[3]);
        *(float4*)&pw[896 + lane * 4] = make_float4(a1e1[0], a1e1[1], a1e1[2], a1e1[3]);
    }
    __syncthreads();

    // reduce across 8 warps, emit bf16 pairs (1024 outputs: 2 i x 512)
    #pragma unroll
    for (int rep = 0; rep < 4; rep++) {
        int o = t + rep * 256;
        float s = 0.0f;
        #pragma unroll
        for (int ww = 0; ww < 8; ww++) s += s_part[ww * 1024 + o];
        int ii = o >> 9, seg = o & 511;
        size_t mo = ((size_t)(b * 64 + i0 + ii)) * 512 + seg;
        __nv_bfloat16 hi, lo; bf16split(s, &hi, &lo);
        g_mhah[mo] = hi; g_mhal[mo] = lo;
    }
}

// ---------------- final mean over nodes ----------------
__global__ void mean_kernel(float* __restrict__ out)
{
    int b = blockIdx.x, d = threadIdx.x;
    float s = 0.0f;
    for (int n = 0; n < 64; n++) s += g_emb[(size_t)(b * 64 + n) * 128 + d];
    out[b * 128 + d] = s * (1.0f / 64.0f);
}

// ============================================================================
// host
// ============================================================================
extern "C" void kernel_launch(void* const* d_in, const int* in_sizes, int n_in,
                              void* d_out, int out_size)
{
    if (n_in < 21) return;
    bool dict = (in_sizes[3] == BB * NNODE * NNODE);

    const float *nf, *st, *ef, *Wn, *bn, *We, *be, *l1g, *l1b,
                *Wq, *Wk, *Wv, *Wo, *bo, *l2g, *l2b, *W1, *b1, *W2, *b2;
    const void* mask;

    if (dict) {
        nf  = (const float*)d_in[0];  st  = (const float*)d_in[1];
        ef  = (const float*)d_in[2];  mask = d_in[3];
        Wn  = (const float*)d_in[4];  bn  = (const float*)d_in[5];
        We  = (const float*)d_in[6];  be  = (const float*)d_in[7];
        l1g = (const float*)d_in[8];  l1b = (const float*)d_in[9];
        Wq  = (const float*)d_in[10]; Wk  = (const float*)d_in[11];
        Wv  = (const float*)d_in[12]; Wo  = (const float*)d_in[13];
        bo  = (const float*)d_in[14]; l2g = (const float*)d_in[15];
        l2b = (const float*)d_in[16]; W1  = (const float*)d_in[17];
        b1  = (const float*)d_in[18]; W2  = (const float*)d_in[19];
        b2  = (const float*)d_in[20];
    } else {
        nf  = (const float*)d_in[0];  st  = (const float*)d_in[1];
        ef  = (const float*)d_in[2];
        Wn  = (const float*)d_in[3];  bn  = (const float*)d_in[4];
        We  = (const float*)d_in[5];  be  = (const float*)d_in[6];
        l1g = (const float*)d_in[7];  l1b = (const float*)d_in[8];
        Wq  = (const float*)d_in[9];  Wk  = (const float*)d_in[10];
        Wv  = (const float*)d_in[11]; Wo  = (const float*)d_in[12];
        bo  = (const float*)d_in[13]; l2g = (const float*)d_in[14];
        l2b = (const float*)d_in[15]; W1  = (const float*)d_in[16];
        b1  = (const float*)d_in[17]; W2  = (const float*)d_in[18];
        b2  = (const float*)d_in[19]; mask = d_in[20];
    }

    float *p_emb, *p_cvec, *p_qkv;
    __nv_bfloat16 *p_x0h, *p_x0l, *p_hh, *p_hl, *p_mhah, *p_mhal, *p_ffh, *p_ffl;
    __nv_bfloat16 *p_WnImg, *p_WprojImg, *p_WbigImg, *p_W1Img, *p_W2Img;
    cudaGetSymbolAddress((void**)&p_emb,   g_emb);
    cudaGetSymbolAddress((void**)&p_cvec,  g_cvec);
    cudaGetSymbolAddress((void**)&p_x0h,   g_x0h);
    cudaGetSymbolAddress((void**)&p_x0l,   g_x0l);
    cudaGetSymbolAddress((void**)&p_hh,    g_hh);
    cudaGetSymbolAddress((void**)&p_hl,    g_hl);
    cudaGetSymbolAddress((void**)&p_mhah,  g_mhah);
    cudaGetSymbolAddress((void**)&p_mhal,  g_mhal);
    cudaGetSymbolAddress((void**)&p_ffh,   g_ffh);
    cudaGetSymbolAddress((void**)&p_ffl,   g_ffl);
    cudaGetSymbolAddress((void**)&p_qkv,   g_qkv);
    cudaGetSymbolAddress((void**)&p_WnImg,   g_WnImg);
    cudaGetSymbolAddress((void**)&p_WprojImg, g_WprojImg);
    cudaGetSymbolAddress((void**)&p_WbigImg,  g_WbigImg);
    cudaGetSymbolAddress((void**)&p_W1Img,    g_W1Img);
    cudaGetSymbolAddress((void**)&p_W2Img,    g_W2Img);

    const int ATTN_SMEM = ATTN_SMEM_FLOATS * 4;
    cudaFuncSetAttribute(attn_kernel, cudaFuncAttributeMaxDynamicSharedMemorySize, ATTN_SMEM);

    float* out = (float*)d_out;
    size_t need_attn = (size_t)BB * DD + (size_t)LLAYERS * NHH * BB * NNODE * NNODE;
    int write_attn = ((size_t)out_size >= need_attn) ? 1 : 0;
    float* attn_base = out + BB * DD;

    // 1: all weight prep fused
    fused_prep<<<PREP_BLOCKS, 256>>>(Wn, Wq, Wk, Wv, We, Wo, W1, W2, be, bo);
    // 2: mask dtype
    detect_mask_kernel<<<1, 256>>>((const unsigned char*)mask);
    // 3: concat
    concat_kernel<<<(ROWS * 64 + 255) / 256, 256>>>(nf, st);
    // 4: Wn GEMM (this launch lands in the ncu capture window)
    mm_mma<<<dim3(2, 64), 128>>>(p_x0h, p_x0l, p_WnImg, 128, 256,
        bn, nullptr, 0, p_emb, 128, nullptr, nullptr, 0, 0);

    for (int l = 0; l < LLAYERS; l++) {
        const float* be_l = be + (size_t)l * 128;
        ln_kernel<<<512, 256>>>(p_emb, l1g + l * 128, l1b + l * 128, 1e-5f);
        mm_mma<<<dim3(16, 64), 128>>>(p_hh, p_hl,
            p_WprojImg + (size_t)l * 2 * 128 * 1024, 1024, 128,
            nullptr, nullptr, 0, p_qkv, 1024, nullptr, nullptr, 0, 0);

        attn_kernel<<<dim3(32, 64), 256, ATTN_SMEM>>>(ef, mask, be_l,
                                                      attn_base, write_attn, l);

        mm_mma<<<dim3(2, 64), 128>>>(p_mhah, p_mhal,
            p_WbigImg + (size_t)l * 2 * 512 * 128, 128, 512,
            p_cvec + l * 128, p_emb, 128, p_emb, 128, nullptr, nullptr, 0, 0);

        ln_kernel<<<512, 256>>>(p_emb, l2g + l * 128, l2b + l * 128, 1e-6f);
        mm_mma<<<dim3(8, 64), 128>>>(p_hh, p_hl,
            p_W1Img + (size_t)l * 2 * 128 * 512, 512, 128,
            b1 + (size_t)l * 512, nullptr, 0, nullptr, 0, p_ffh, p_ffl, 512, 1);
        mm_mma<<<dim3(2, 64), 128>>>(p_ffh, p_ffl,
            p_W2Img + (size_t)l * 2 * 512 * 128, 128, 512,
            b2 + (size_t)l * 128, p_emb, 128, p_emb, 128, nullptr, nullptr, 0, 0);
    }

    mean_kernel<<<BB, 128>>>(out);
}

// round 9
// speedup vs baseline: 2.2699x; 1.1380x over previous
#include <cuda_runtime.h>
#include <cuda_bf16.h>
#include <math.h>
#include <stdint.h>

// Problem dims
#define BB 64
#define NNODE 64
#define DD 128
#define NHH 2
#define LLAYERS 2
#define ROWS (BB*NNODE)          // 4096

// ============================================================================
// Helpers
// ============================================================================
__device__ __forceinline__ uint32_t smem_u32(const void* p) {
    uint32_t a;
    asm("{ .reg .u64 t; cvta.to.shared.u64 t, %1; cvt.u32.u64 %0, t; }"
        : "=r"(a) : "l"(p));
    return a;
}

__device__ __forceinline__ void ldmA(uint32_t* a, uint32_t addr) {
    asm volatile("ldmatrix.sync.aligned.m8n8.x4.shared.b16 {%0,%1,%2,%3}, [%4];"
        : "=r"(a[0]), "=r"(a[1]), "=r"(a[2]), "=r"(a[3]) : "r"(addr));
}
__device__ __forceinline__ void ldmBt(uint32_t* b, uint32_t addr) {
    asm volatile("ldmatrix.sync.aligned.m8n8.x2.trans.shared.b16 {%0,%1}, [%2];"
        : "=r"(b[0]), "=r"(b[1]) : "r"(addr));
}
__device__ __forceinline__ void mma16816(float* d, const uint32_t* a, const uint32_t* b) {
    asm volatile("mma.sync.aligned.m16n8k16.row.col.f32.bf16.bf16.f32 "
        "{%0,%1,%2,%3}, {%4,%5,%6,%7}, {%8,%9}, {%0,%1,%2,%3};"
        : "+f"(d[0]), "+f"(d[1]), "+f"(d[2]), "+f"(d[3])
        : "r"(a[0]), "r"(a[1]), "r"(a[2]), "r"(a[3]), "r"(b[0]), "r"(b[1]));
}
__device__ __forceinline__ void cp16(uint32_t saddr, const void* gptr) {
    asm volatile("cp.async.cg.shared.global [%0], [%1], 16;"
        :: "r"(saddr), "l"(gptr));
}
#define CP_COMMIT() asm volatile("cp.async.commit_group;" ::: "memory")
template <int N>
__device__ __forceinline__ void cp_wait() {
    asm volatile("cp.async.wait_group %0;" :: "n"(N) : "memory");
}

__device__ __forceinline__ void bf16split(float v, __nv_bfloat16* hi, __nv_bfloat16* lo) {
    __nv_bfloat16 h = __float2bfloat16(v);
    *hi = h;
    *lo = __float2bfloat16(v - __bfloat162float(h));
}

// ============================================================================
// Scratch (device globals; no allocation)
// ============================================================================
__device__ __nv_bfloat16 g_x0h [ROWS*256];
__device__ __nv_bfloat16 g_x0l [ROWS*256];
__device__ float         g_emb [ROWS*128];
__device__ __nv_bfloat16 g_hh  [ROWS*128];
__device__ __nv_bfloat16 g_hl  [ROWS*128];
__device__ float         g_qkv [ROWS*1024];
__device__ __nv_bfloat16 g_mhah[ROWS*512];
__device__ __nv_bfloat16 g_mhal[ROWS*512];
__device__ __nv_bfloat16 g_ffh [ROWS*512];
__device__ __nv_bfloat16 g_ffl [ROWS*512];
__device__ float         g_cvec[LLAYERS*128];
__device__ int           g_mask_mode;

// Weight images, natural [K][N] bf16, hi plane then lo plane
__device__ __nv_bfloat16 g_WnImg  [2*256*128];
__device__ __nv_bfloat16 g_WprojImg[LLAYERS][2*128*1024];
__device__ __nv_bfloat16 g_WbigImg [LLAYERS][2*512*128];
__device__ __nv_bfloat16 g_W1Img   [LLAYERS][2*128*512];
__device__ __nv_bfloat16 g_W2Img   [LLAYERS][2*512*128];

// ============================================================================
// mask dtype detection (parallel)
// ============================================================================
__global__ void detect_mask_kernel(const unsigned char* __restrict__ m)
{
    __shared__ int cnt[2];
    if (threadIdx.x < 2) cnt[threadIdx.x] = 0;
    __syncthreads();
    int u8 = 0, f32 = 0;
    for (int i = threadIdx.x; i < 4096; i += 256) {
        unsigned char v = m[i];
        if (v) {
            int r = i & 3;
            if (r == 1) u8++;
            else if (r == 3) f32++;
        }
    }
    if (u8)  atomicAdd(&cnt[0], u8);
    if (f32) atomicAdd(&cnt[1], f32);
    __syncthreads();
    if (threadIdx.x == 0)
        g_mask_mode = cnt[0] ? 0 : (cnt[1] ? 2 : 1);
}
__device__ __forceinline__ bool mask_at(const void* mp, size_t idx, int mode)
{
    if (mode == 0) return ((const unsigned char*)mp)[idx] != 0;
    if (mode == 1) return ((const int*)mp)[idx] != 0;
    return ((const float*)mp)[idx] != 0.0f;
}

// ============================================================================
// Fused prologue: ALL weight-image prep in one kernel (blockIdx dispatch)
// ============================================================================
#define PREP_BLOCKS (128 + 768 + 256 + 256 + 256 + 512 + 512 + 1)
__global__ void fused_prep(const float* __restrict__ Wn, const float* __restrict__ Wq,
                           const float* __restrict__ Wk, const float* __restrict__ Wv,
                           const float* __restrict__ We, const float* __restrict__ Wo,
                           const float* __restrict__ W1, const float* __restrict__ W2,
                           const float* __restrict__ be, const float* __restrict__ bo)
{
    int blk = blockIdx.x, tid = threadIdx.x;
    __nv_bfloat16 hi, lo;

    if (blk < 128) {
        int t = blk * 256 + tid;
        bf16split(Wn[t], &hi, &lo);
        g_WnImg[t] = hi; g_WnImg[32768 + t] = lo;
        return;
    }
    blk -= 128;
    if (blk < 768) {
        int idx = blk * 256 + tid;
        int l = idx / 98304, r = idx % 98304;
        int k = r / 768, n = r % 768;
        const float* W = (n < 256) ? Wq : (n < 512 ? Wk : Wv);
        float v = W[(size_t)l * 32768 + (size_t)k * 256 + (n & 255)];
        bf16split(v, &hi, &lo);
        g_WprojImg[l][(size_t)k * 1024 + n]          = hi;
        g_WprojImg[l][131072 + (size_t)k * 1024 + n] = lo;
        return;
    }
    blk -= 768;
    if (blk < 256) {
        int idx = blk * 256 + tid;
        int l = idx >> 15, r = idx & 32767;
        int h = r >> 14, r2 = r & 16383;
        int e = r2 >> 7, d = r2 & 127;
        const float* wq = Wq + (size_t)l * 32768 + (size_t)d * 256 + h * 128;
        const float* we = We + (size_t)l * 16384 + (size_t)e * 128;
        float acc = 0.0f;
        #pragma unroll 8
        for (int c = 0; c < 128; c++) acc += wq[c] * we[c];
        size_t o = (size_t)d * 1024 + 768 + h * 128 + e;
        bf16split(acc, &hi, &lo);
        g_WprojImg[l][o] = hi; g_WprojImg[l][131072 + o] = lo;
        return;
    }
    blk -= 256;
    if (blk < 256) {
        int idx = blk * 256 + tid;
        int l = idx >> 15, t2 = idx & 32767;
        bf16split(Wo[(size_t)l * 32768 + t2], &hi, &lo);
        g_WbigImg[l][t2] = hi; g_WbigImg[l][65536 + t2] = lo;
        return;
    }
    blk -= 256;
    if (blk < 256) {
        int idx = blk * 256 + tid;
        int l = idx >> 15, r = idx & 32767;
        int h = r >> 14, r2 = r & 16383;
        int f = r2 >> 7, n = r2 & 127;
        const float* we = We + (size_t)l * 16384 + (size_t)f * 128;
        const float* wo = Wo + (size_t)l * 32768 + (size_t)(h * 128) * 128 + n;
        float acc = 0.0f;
        #pragma unroll 8
        for (int e = 0; e < 128; e++) acc += we[e] * wo[(size_t)e * 128];
        size_t o = (size_t)(256 + h * 128 + f) * 128 + n;
        bf16split(acc, &hi, &lo);
        g_WbigImg[l][o] = hi; g_WbigImg[l][65536 + o] = lo;
        return;
    }
    blk -= 256;
    if (blk < 512) {
        int idx = blk * 256 + tid;
        int l = idx >> 16, t2 = idx & 65535;
        bf16split(W1[(size_t)l * 65536 + t2], &hi, &lo);
        g_W1Img[l][t2] = hi; g_W1Img[l][65536 + t2] = lo;
        return;
    }
    blk -= 512;
    if (blk < 512) {
        int idx = blk * 256 + tid;
        int l = idx >> 16, t2 = idx & 65535;
        bf16split(W2[(size_t)l * 65536 + t2], &hi, &lo);
        g_W2Img[l][t2] = hi; g_W2Img[l][65536 + t2] = lo;
        return;
    }
    blk -= 512;
    {
        int l = tid >> 7, d = tid & 127;
        float acc = bo[l * 128 + d];
        const float* wo = Wo + (size_t)l * 32768;
        const float* bel = be + l * 128;
        for (int r = 0; r < 256; r++) acc += bel[r & 127] * wo[(size_t)r * 128 + d];
        g_cvec[l * 128 + d] = acc;
    }
}

// ============================================================================
// concat(node_feat, stpe) -> bf16 pairs [4096,256]
// ============================================================================
__global__ void concat_kernel(const float* __restrict__ nf, const float* __restrict__ st)
{
    int t = blockIdx.x * blockDim.x + threadIdx.x;
    if (t < ROWS * 64) {
        int row = t >> 6, c4 = t & 63;
        float4 val = (c4 < 32) ? ((const float4*)nf)[row * 32 + c4]
                               : ((const float4*)st)[row * 32 + (c4 - 32)];
        size_t o = (size_t)row * 256 + c4 * 4;
        float vv[4] = {val.x, val.y, val.z, val.w};
        #pragma unroll
        for (int j = 0; j < 4; j++) {
            __nv_bfloat16 hi, lo; bf16split(vv[j], &hi, &lo);
            g_x0h[o + j] = hi; g_x0l[o + j] = lo;
        }
    }
}

// ============================================================================
// LayerNorm -> bf16 pairs
// ============================================================================
__global__ void ln_kernel(const float* __restrict__ x,
                          const float* __restrict__ g, const float* __restrict__ b,
                          float eps)
{
    int row  = blockIdx.x * 8 + (threadIdx.x >> 5);
    int lane = threadIdx.x & 31;
    const float* xr = x + (size_t)row * 128;
    float v0 = xr[lane], v1 = xr[lane + 32], v2 = xr[lane + 64], v3 = xr[lane + 96];
    float s = v0 + v1 + v2 + v3;
    #pragma unroll
    for (int o = 16; o; o >>= 1) s += __shfl_xor_sync(0xffffffffu, s, o);
    float mu = s * (1.0f / 128.0f);
    float d0 = v0 - mu, d1 = v1 - mu, d2 = v2 - mu, d3 = v3 - mu;
    float q = d0*d0 + d1*d1 + d2*d2 + d3*d3;
    #pragma unroll
    for (int o = 16; o; o >>= 1) q += __shfl_xor_sync(0xffffffffu, q, o);
    float inv = rsqrtf(q * (1.0f / 128.0f) + eps);
    size_t base = (size_t)row * 128;
    float y0 = d0 * inv * g[lane]      + b[lane];
    float y1 = d1 * inv * g[lane + 32] + b[lane + 32];
    float y2 = d2 * inv * g[lane + 64] + b[lane + 64];
    float y3 = d3 * inv * g[lane + 96] + b[lane + 96];
    __nv_bfloat16 hi, lo;
    bf16split(y0, &hi, &lo); g_hh[base + lane]      = hi; g_hl[base + lane]      = lo;
    bf16split(y1, &hi, &lo); g_hh[base + lane + 32] = hi; g_hl[base + lane + 32] = lo;
    bf16split(y2, &hi, &lo); g_hh[base + lane + 64] = hi; g_hl[base + lane + 64] = lo;
    bf16split(y3, &hi, &lo); g_hh[base + lane + 96] = hi; g_hl[base + lane + 96] = lo;
}

// ============================================================================
// mma.sync GEMM with cp.async double-buffering.
// 64x64 tile, 128 threads = 4 warps (2m x 2n), warp tile 32x32, K-chunk 32.
// ============================================================================
#define AKP 40
#define BNP 72
__global__ __launch_bounds__(128) void mm_mma(
    const __nv_bfloat16* __restrict__ Ah, const __nv_bfloat16* __restrict__ Al,
    const __nv_bfloat16* __restrict__ Wimg, int N, int K,
    const float* __restrict__ bias,
    const float* __restrict__ res, int ldr,
    float* __restrict__ outf, int ldo,
    __nv_bfloat16* __restrict__ oh, __nv_bfloat16* __restrict__ ol, int ldp,
    int relu)
{
    __shared__ __nv_bfloat16 sA[2][2][64 * AKP];   // [stage][hi/lo]
    __shared__ __nv_bfloat16 sB[2][2][32 * BNP];

    int tid = threadIdx.x, lane = tid & 31, wid = tid >> 5;
    int m0 = blockIdx.y * 64, n0 = blockIdx.x * 64;
    int wm = (wid >> 1) * 32, wn = (wid & 1) * 32;

    const __nv_bfloat16* Wh = Wimg;
    const __nv_bfloat16* Wl = Wimg + (size_t)N * K;

    float acc[2][4][4];
    #pragma unroll
    for (int mt = 0; mt < 2; mt++)
        #pragma unroll
        for (int nt = 0; nt < 4; nt++)
            #pragma unroll
            for (int c = 0; c < 4; c++) acc[mt][nt][c] = 0.0f;

    uint32_t sA_b[2][2], sB_b[2][2];
    #pragma unroll
    for (int s = 0; s < 2; s++)
        #pragma unroll
        for (int p = 0; p < 2; p++) {
            sA_b[s][p] = smem_u32(sA[s][p]);
            sB_b[s][p] = smem_u32(sB[s][p]);
        }

    int ar0 = tid >> 2, ac0 = (tid & 3) * 8;
    int br0 = tid >> 3, bc0 = (tid & 7) * 8;

    int la_row = lane & 15, la_col = (lane >> 4) * 8;
    int lb_row = lane & 15;

    int nch = K >> 5;

    // prefetch chunk 0 into stage 0
    {
        int k0 = 0;
        #pragma unroll
        for (int i = 0; i < 2; i++) {
            int ar = ar0 + i * 32;
            cp16(sA_b[0][0] + (uint32_t)(ar * AKP + ac0) * 2,
                 Ah + (size_t)(m0 + ar) * K + k0 + ac0);
            cp16(sA_b[0][1] + (uint32_t)(ar * AKP + ac0) * 2,
                 Al + (size_t)(m0 + ar) * K + k0 + ac0);
            int br = br0 + i * 16;
            cp16(sB_b[0][0] + (uint32_t)(br * BNP + bc0) * 2,
                 Wh + (size_t)(k0 + br) * N + n0 + bc0);
            cp16(sB_b[0][1] + (uint32_t)(br * BNP + bc0) * 2,
                 Wl + (size_t)(k0 + br) * N + n0 + bc0);
        }
        CP_COMMIT();
    }

    for (int ch = 0; ch < nch; ch++) {
        int st = ch & 1;
        bool more = (ch + 1 < nch);
        if (more) {
            int k0 = (ch + 1) << 5;
            int s2 = st ^ 1;
            #pragma unroll
            for (int i = 0; i < 2; i++) {
                int ar = ar0 + i * 32;
                cp16(sA_b[s2][0] + (uint32_t)(ar * AKP + ac0) * 2,
                     Ah + (size_t)(m0 + ar) * K + k0 + ac0);
                cp16(sA_b[s2][1] + (uint32_t)(ar * AKP + ac0) * 2,
                     Al + (size_t)(m0 + ar) * K + k0 + ac0);
                int br = br0 + i * 16;
                cp16(sB_b[s2][0] + (uint32_t)(br * BNP + bc0) * 2,
                     Wh + (size_t)(k0 + br) * N + n0 + bc0);
                cp16(sB_b[s2][1] + (uint32_t)(br * BNP + bc0) * 2,
                     Wl + (size_t)(k0 + br) * N + n0 + bc0);
            }
            CP_COMMIT();
            cp_wait<1>();
        } else {
            cp_wait<0>();
        }
        __syncthreads();

        #pragma unroll
        for (int ks = 0; ks < 2; ks++) {
            int kb = ks * 16;
            uint32_t bH[4][2], bL[4][2];
            #pragma unroll
            for (int nt = 0; nt < 4; nt++) {
                uint32_t boff = (uint32_t)((kb + lb_row) * BNP + wn + nt * 8) * 2;
                ldmBt(bH[nt], sB_b[st][0] + boff);
                ldmBt(bL[nt], sB_b[st][1] + boff);
            }
            #pragma unroll
            for (int mt = 0; mt < 2; mt++) {
                uint32_t aoff = (uint32_t)((wm + mt * 16 + la_row) * AKP + kb + la_col) * 2;
                uint32_t aH[4], aL[4];
                ldmA(aH, sA_b[st][0] + aoff);
                ldmA(aL, sA_b[st][1] + aoff);
                #pragma unroll
                for (int nt = 0; nt < 4; nt++) {
                    mma16816(acc[mt][nt], aH, bH[nt]);
                    mma16816(acc[mt][nt], aH, bL[nt]);
                    mma16816(acc[mt][nt], aL, bH[nt]);
                }
            }
        }
        __syncthreads();
    }

    int g = lane >> 2, tg = lane & 3;
    #pragma unroll
    for (int mt = 0; mt < 2; mt++) {
        #pragma unroll
        for (int nt = 0; nt < 4; nt++) {
            int col = n0 + wn + nt * 8 + tg * 2;
            #pragma unroll
            for (int half = 0; half < 2; half++) {
                int row = m0 + wm + mt * 16 + g + half * 8;
                float v0 = acc[mt][nt][half * 2];
                float v1 = acc[mt][nt][half * 2 + 1];
                if (bias) { v0 += bias[col]; v1 += bias[col + 1]; }
                if (res) {
                    v0 += res[(size_t)row * ldr + col];
                    v1 += res[(size_t)row * ldr + col + 1];
                }
                if (relu) { v0 = fmaxf(v0, 0.0f); v1 = fmaxf(v1, 0.0f); }
                if (outf) {
                    outf[(size_t)row * ldo + col]     = v0;
                    outf[(size_t)row * ldo + col + 1] = v1;
                }
                if (oh) {
                    __nv_bfloat16 hi, lo;
                    bf16split(v0, &hi, &lo);
                    oh[(size_t)row * ldp + col] = hi;
                    ol[(size_t)row * ldp + col] = lo;
                    bf16split(v1, &hi, &lo);
                    oh[(size_t)row * ldp + col + 1] = hi;
                    ol[(size_t)row * ldp + col + 1] = lo;
                }
            }
        }
    }
}

// ============================================================================
// fused attention v3 — 2 query rows per CTA (unchanged)
// ============================================================================
#define ATTN_SMEM_FLOATS (16384 + 8192 + 512 + 512 + 256 + 256 + 128)
__global__ __launch_bounds__(256) void attn_kernel(
    const float* __restrict__ edge,
    const void* __restrict__ mask,
    const float* __restrict__ be_l,
    float* __restrict__ attn_out, int write_attn,
    int layer)
{
    extern __shared__ float sm[];
    float* s_e    = sm;
    float* s_part = s_e + 16384;
    float* s_q    = s_part + 8192;
    float* s_qe   = s_q + 512;
    float* s_sc   = s_qe + 512;
    float* s_att  = s_sc + 256;
    float* s_be   = s_att + 256;

    int b = blockIdx.y, i0 = blockIdx.x * 2;
    int t = threadIdx.x, lane = t & 31, w = t >> 5;
    int mode = g_mask_mode;
    size_t qrow0 = (size_t)(b * 64 + i0) * 1024;

    const float4* esrc = (const float4*)(edge + ((size_t)(b * 64 + i0)) * 8192);
    #pragma unroll
    for (int r = 0; r < 16; r++)
        ((float4*)s_e)[t + r * 256] = esrc[t + r * 256];
    s_q [t]       = g_qkv[qrow0 + t];
    s_q [256 + t] = g_qkv[qrow0 + 1024 + t];
    s_qe[t]       = g_qkv[qrow0 + 768 + t];
    s_qe[256 + t] = g_qkv[qrow0 + 1024 + 768 + t];
    if (t < 128) s_be[t] = be_l[t];
    __syncthreads();

    {
        int h = w >> 2;
        float4 q0  = *(float4*)&s_q [h * 128 + lane * 4];
        float4 q1  = *(float4*)&s_q [256 + h * 128 + lane * 4];
        float4 qe0 = *(float4*)&s_qe[h * 128 + lane * 4];
        float4 qe1 = *(float4*)&s_qe[256 + h * 128 + lane * 4];
        float4 be4 = *(float4*)&s_be[lane * 4];
        float qb0 = q0.x*be4.x + q0.y*be4.y + q0.z*be4.z + q0.w*be4.w;
        float qb1 = q1.x*be4.x + q1.y*be4.y + q1.z*be4.z + q1.w*be4.w;
        #pragma unroll
        for (int off = 16; off; off >>= 1) {
            qb0 += __shfl_xor_sync(0xffffffffu, qb0, off);
            qb1 += __shfl_xor_sync(0xffffffffu, qb1, off);
        }

        #pragma unroll
        for (int oo = 0; oo < 16; oo++) {
            int j = (w & 3) * 16 + oo;
            float4 k4 = *(const float4*)(g_qkv + (size_t)(b * 64 + j) * 1024
                                         + 256 + h * 128 + lane * 4);
            float4 e0 = *(float4*)&s_e[j * 128 + lane * 4];
            float4 e1 = *(float4*)&s_e[8192 + j * 128 + lane * 4];
            float d0 = q0.x*k4.x + q0.y*k4.y + q0.z*k4.z + q0.w*k4.w
                     + qe0.x*e0.x + qe0.y*e0.y + qe0.z*e0.z + qe0.w*e0.w;
            float d1 = q1.x*k4.x + q1.y*k4.y + q1.z*k4.z + q1.w*k4.w
                     + qe1.x*e1.x + qe1.y*e1.y + qe1.z*e1.z + qe1.w*e1.w;
            #pragma unroll
            for (int off = 16; off; off >>= 1) {
                d0 += __shfl_xor_sync(0xffffffffu, d0, off);
                d1 += __shfl_xor_sync(0xffffffffu, d1, off);
            }
            if (lane == 0) {
                s_sc[h * 64 + j]       = d0 + qb0;
                s_sc[128 + h * 64 + j] = d1 + qb1;
            }
        }
    }
    __syncthreads();

    if (w < 4) {
        const float invT = 0.08838834764831843f;
        int ii = w >> 1, h = w & 1;
        int iabs = i0 + ii;
        size_t mbase = ((size_t)(b * 64 + iabs)) * 64;
        float v0 = s_sc[ii * 128 + h * 64 + lane]      * invT;
        float v1 = s_sc[ii * 128 + h * 64 + lane + 32] * invT;
        if (mask_at(mask, mbase + lane,      mode)) v0 = 1e-10f;
        if (mask_at(mask, mbase + lane + 32, mode)) v1 = 1e-10f;
        float mx = fmaxf(v0, v1);
        #pragma unroll
        for (int off = 16; off; off >>= 1)
            mx = fmaxf(mx, __shfl_xor_sync(0xffffffffu, mx, off));
        float e0 = expf(v0 - mx), e1 = expf(v1 - mx);
        float s = e0 + e1;
        #pragma unroll
        for (int off = 16; off; off >>= 1)
            s += __shfl_xor_sync(0xffffffffu, s, off);
        float inv = 1.0f / s;
        e0 *= inv; e1 *= inv;
        s_att[ii * 128 + h * 64 + lane]      = e0;
        s_att[ii * 128 + h * 64 + lane + 32] = e1;
        if (write_attn) {
            float* ap = attn_out +
                ((((size_t)layer * NHH + h) * BB + b) * NNODE + iabs) * NNODE;
            ap[lane]      = e0;
            ap[lane + 32] = e1;
        }
    }
    __syncthreads();

    {
        float a0h0[4] = {}, a0h1[4] = {}, a0e0[4] = {}, a0e1[4] = {};
        float a1h0[4] = {}, a1h1[4] = {}, a1e0[4] = {}, a1e1[4] = {};
        #pragma unroll
        for (int jj = 0; jj < 8; jj++) {
            int j = w + jj * 8;
            const float* vrow = g_qkv + (size_t)(b * 64 + j) * 1024 + 512;
            float4 v0 = *(const float4*)(vrow + lane * 4);
            float4 v1 = *(const float4*)(vrow + 128 + lane * 4);
            float4 e0 = *(float4*)&s_e[j * 128 + lane * 4];
            float4 e1 = *(float4*)&s_e[8192 + j * 128 + lane * 4];
            float w00 = s_att[j],       w01 = s_att[64 + j];
            float w10 = s_att[128 + j], w11 = s_att[192 + j];
            a0h0[0] += w00*v0.x; a0h0[1] += w00*v0.y; a0h0[2] += w00*v0.z; a0h0[3] += w00*v0.w;
            a0h1[0] += w01*v1.x; a0h1[1] += w01*v1.y; a0h1[2] += w01*v1.z; a0h1[3] += w01*v1.w;
            a0e0[0] += w00*e0.x; a0e0[1] += w00*e0.y; a0e0[2] += w00*e0.z; a0e0[3] += w00*e0.w;
            a0e1[0] += w01*e0.x; a0e1[1] += w01*e0.y; a0e1[2] += w01*e0.z; a0e1[3] += w01*e0.w;
            a1h0[0] += w10*v0.x; a1h0[1] += w10*v0.y; a1h0[2] += w10*v0.z; a1h0[3] += w10*v0.w;
            a1h1[0] += w11*v1.x; a1h1[1] += w11*v1.y; a1h1[2] += w11*v1.z; a1h1[3] += w11*v1.w;
            a1e0[0] += w10*e1.x; a1e0[1] += w10*e1.y; a1e0[2] += w10*e1.z; a1e0[3] += w10*e1.w;
            a1e1[0] += w11*e1.x; a1e1[1] += w11*e1.y; a1e1[2] += w11*e1.z; a1e1[3] += w11*e1.w;
        }
        float* pw = s_part + w * 1024;
        *(float4*)&pw[lane * 4]       = make_float4(a0h0[0], a0h0[1], a0h0[2], a0h0[3]);
        *(float4*)&pw[128 + lane * 4] = make_float4(a0h1[0], a0h1[1], a0h1[2], a0h1[3]);
        *(float4*)&pw[256 + lane * 4] = make_float4(a0e0[0], a0e0[1], a0e0[2], a0e0[3]);
        *(float4*)&pw[384 + lane * 4] = make_float4(a0e1[0], a0e1[1], a0e1[2], a0e1[3]);
        *(float4*)&pw[512 + lane * 4] = make_float4(a1h0[0], a1h0[1], a1h0[2], a1h0[3]);
        *(float4*)&pw[640 + lane * 4] = make_float4(a1h1[0], a1h1[1], a1h1[2], a1h1[3]);
        *(float4*)&pw[768 + lane * 4] = make_float4(a1e0[0], a1e0[1], a1e0[2], a1e0[3]);
        *(float4*)&pw[896 + lane * 4] = make_float4(a1e1[0], a1e1[1], a1e1[2], a1e1[3]);
    }
    __syncthreads();

    #pragma unroll
    for (int rep = 0; rep < 4; rep++) {
        int o = t + rep * 256;
        float s = 0.0f;
        #pragma unroll
        for (int ww = 0; ww < 8; ww++) s += s_part[ww * 1024 + o];
        int ii = o >> 9, seg = o & 511;
        size_t mo = ((size_t)(b * 64 + i0 + ii)) * 512 + seg;
        __nv_bfloat16 hi, lo; bf16split(s, &hi, &lo);
        g_mhah[mo] = hi; g_mhal[mo] = lo;
    }
}

// ---------------- final mean over nodes ----------------
__global__ void mean_kernel(float* __restrict__ out)
{
    int b = blockIdx.x, d = threadIdx.x;
    float s = 0.0f;
    for (int n = 0; n < 64; n++) s += g_emb[(size_t)(b * 64 + n) * 128 + d];
    out[b * 128 + d] = s * (1.0f / 64.0f);
}

// ============================================================================
// host
// ============================================================================
extern "C" void kernel_launch(void* const* d_in, const int* in_sizes, int n_in,
                              void* d_out, int out_size)
{
    if (n_in < 21) return;
    bool dict = (in_sizes[3] == BB * NNODE * NNODE);

    const float *nf, *st, *ef, *Wn, *bn, *We, *be, *l1g, *l1b,
                *Wq, *Wk, *Wv, *Wo, *bo, *l2g, *l2b, *W1, *b1, *W2, *b2;
    const void* mask;

    if (dict) {
        nf  = (const float*)d_in[0];  st  = (const float*)d_in[1];
        ef  = (const float*)d_in[2];  mask = d_in[3];
        Wn  = (const float*)d_in[4];  bn  = (const float*)d_in[5];
        We  = (const float*)d_in[6];  be  = (const float*)d_in[7];
        l1g = (const float*)d_in[8];  l1b = (const float*)d_in[9];
        Wq  = (const float*)d_in[10]; Wk  = (const float*)d_in[11];
        Wv  = (const float*)d_in[12]; Wo  = (const float*)d_in[13];
        bo  = (const float*)d_in[14]; l2g = (const float*)d_in[15];
        l2b = (const float*)d_in[16]; W1  = (const float*)d_in[17];
        b1  = (const float*)d_in[18]; W2  = (const float*)d_in[19];
        b2  = (const float*)d_in[20];
    } else {
        nf  = (const float*)d_in[0];  st  = (const float*)d_in[1];
        ef  = (const float*)d_in[2];
        Wn  = (const float*)d_in[3];  bn  = (const float*)d_in[4];
        We  = (const float*)d_in[5];  be  = (const float*)d_in[6];
        l1g = (const float*)d_in[7];  l1b = (const float*)d_in[8];
        Wq  = (const float*)d_in[9];  Wk  = (const float*)d_in[10];
        Wv  = (const float*)d_in[11]; Wo  = (const float*)d_in[12];
        bo  = (const float*)d_in[13]; l2g = (const float*)d_in[14];
        l2b = (const float*)d_in[15]; W1  = (const float*)d_in[16];
        b1  = (const float*)d_in[17]; W2  = (const float*)d_in[18];
        b2  = (const float*)d_in[19]; mask = d_in[20];
    }

    float *p_emb, *p_cvec, *p_qkv;
    __nv_bfloat16 *p_x0h, *p_x0l, *p_hh, *p_hl, *p_mhah, *p_mhal, *p_ffh, *p_ffl;
    __nv_bfloat16 *p_WnImg, *p_WprojImg, *p_WbigImg, *p_W1Img, *p_W2Img;
    cudaGetSymbolAddress((void**)&p_emb,   g_emb);
    cudaGetSymbolAddress((void**)&p_cvec,  g_cvec);
    cudaGetSymbolAddress((void**)&p_x0h,   g_x0h);
    cudaGetSymbolAddress((void**)&p_x0l,   g_x0l);
    cudaGetSymbolAddress((void**)&p_hh,    g_hh);
    cudaGetSymbolAddress((void**)&p_hl,    g_hl);
    cudaGetSymbolAddress((void**)&p_mhah,  g_mhah);
    cudaGetSymbolAddress((void**)&p_mhal,  g_mhal);
    cudaGetSymbolAddress((void**)&p_ffh,   g_ffh);
    cudaGetSymbolAddress((void**)&p_ffl,   g_ffl);
    cudaGetSymbolAddress((void**)&p_qkv,   g_qkv);
    cudaGetSymbolAddress((void**)&p_WnImg,   g_WnImg);
    cudaGetSymbolAddress((void**)&p_WprojImg, g_WprojImg);
    cudaGetSymbolAddress((void**)&p_WbigImg,  g_WbigImg);
    cudaGetSymbolAddress((void**)&p_W1Img,    g_W1Img);
    cudaGetSymbolAddress((void**)&p_W2Img,    g_W2Img);

    const int ATTN_SMEM = ATTN_SMEM_FLOATS * 4;
    cudaFuncSetAttribute(attn_kernel, cudaFuncAttributeMaxDynamicSharedMemorySize, ATTN_SMEM);

    float* out = (float*)d_out;
    size_t need_attn = (size_t)BB * DD + (size_t)LLAYERS * NHH * BB * NNODE * NNODE;
    int write_attn = ((size_t)out_size >= need_attn) ? 1 : 0;
    float* attn_base = out + BB * DD;

    fused_prep<<<PREP_BLOCKS, 256>>>(Wn, Wq, Wk, Wv, We, Wo, W1, W2, be, bo);
    detect_mask_kernel<<<1, 256>>>((const unsigned char*)mask);
    concat_kernel<<<(ROWS * 64 + 255) / 256, 256>>>(nf, st);
    // 4th launch: Wn GEMM (stays in the ncu capture slot for A/B comparison)
    mm_mma<<<dim3(2, 64), 128>>>(p_x0h, p_x0l, p_WnImg, 128, 256,
        bn, nullptr, 0, p_emb, 128, nullptr, nullptr, 0, 0);

    for (int l = 0; l < LLAYERS; l++) {
        const float* be_l = be + (size_t)l * 128;
        ln_kernel<<<512, 256>>>(p_emb, l1g + l * 128, l1b + l * 128, 1e-5f);
        mm_mma<<<dim3(16, 64), 128>>>(p_hh, p_hl,
            p_WprojImg + (size_t)l * 2 * 128 * 1024, 1024, 128,
            nullptr, nullptr, 0, p_qkv, 1024, nullptr, nullptr, 0, 0);

        attn_kernel<<<dim3(32, 64), 256, ATTN_SMEM>>>(ef, mask, be_l,
                                                      attn_base, write_attn, l);

        mm_mma<<<dim3(2, 64), 128>>>(p_mhah, p_mhal,
            p_WbigImg + (size_t)l * 2 * 512 * 128, 128, 512,
            p_cvec + l * 128, p_emb, 128, p_emb, 128, nullptr, nullptr, 0, 0);

        ln_kernel<<<512, 256>>>(p_emb, l2g + l * 128, l2b + l * 128, 1e-6f);
        mm_mma<<<dim3(8, 64), 128>>>(p_hh, p_hl,
            p_W1Img + (size_t)l * 2 * 128 * 512, 512, 128,
            b1 + (size_t)l * 512, nullptr, 0, nullptr, 0, p_ffh, p_ffl, 512, 1);
        mm_mma<<<dim3(2, 64), 128>>>(p_ffh, p_ffl,
            p_W2Img + (size_t)l * 2 * 512 * 128, 128, 512,
            b2 + (size_t)l * 128, p_emb, 128, p_emb, 128, nullptr, nullptr, 0, 0);
    }

    mean_kernel<<<BB, 128>>>(out);
}